// round 5
// baseline (speedup 1.0000x reference)
#include <cuda_runtime.h>
#include <cstdint>

#define N_TOK   49
#define C_DIM   256
#define H_NUM   8
#define HD      32
#define B_WIN   4096
#define M_ROWS  (B_WIN * N_TOK)   // 200704

// Scratch (allocation-free rule: __device__ globals)
__device__ float g_qkv[(size_t)B_WIN * H_NUM * 3 * N_TOK * HD];   // 616 MB
__device__ float g_attn[(size_t)M_ROWS * C_DIM];                  // 205 MB

// ---------------------------------------------------------------------------
__device__ __forceinline__ float to_tf32(float x) {
    uint32_t u;
    asm("cvt.rna.tf32.f32 %0, %1;" : "=r"(u) : "f"(x));
    return __uint_as_float(u);
}

__device__ __forceinline__ void mma_tf32(float c[4], const uint32_t a[4], const uint32_t b[2]) {
    asm volatile(
        "mma.sync.aligned.m16n8k8.row.col.f32.tf32.tf32.f32 "
        "{%0,%1,%2,%3}, {%4,%5,%6,%7}, {%8,%9}, {%0,%1,%2,%3};"
        : "+f"(c[0]), "+f"(c[1]), "+f"(c[2]), "+f"(c[3])
        : "r"(a[0]), "r"(a[1]), "r"(a[2]), "r"(a[3]), "r"(b[0]), "r"(b[1]));
}

// ---------------------------------------------------------------------------
// GEMM: CTA tile 128x128, warp tile 64x32 (8 warps: 2 along M x 4 along N).
// X row-major [M,256]; W row-major [N,256] (== B col-major for row.col mma).
//   QKV_MODE=true : epilogue scatters (bias, q-scale) into g_qkv
//   QKV_MODE=false: epilogue writes (bias) to out
// ---------------------------------------------------------------------------
template<bool QKV_MODE>
__global__ __launch_bounds__(256) void gemm128(
    const float* __restrict__ Xin, const float* __restrict__ W,
    const float* __restrict__ bias, float* __restrict__ out)
{
    __shared__ float As[128][36];
    __shared__ float Bs[128][36];
    const int tid = threadIdx.x;
    const int mBase = blockIdx.x * 128;
    const int nBase = blockIdx.y * 128;
    const float* X = QKV_MODE ? Xin : (const float*)g_attn;

    const int warp = tid >> 5, lane = tid & 31;
    const int wm = (warp & 1) * 64, wn = (warp >> 1) * 32;
    const int g = lane >> 2, t = lane & 3;

    float acc[4][4][4] = {};   // [mi][ni][4]

    for (int kc = 0; kc < 256; kc += 32) {
#pragma unroll
        for (int p = 0; p < 4; p++) {
            int idx = tid + p * 256;           // 1024 float4 per operand
            int r = idx >> 3, c = (idx & 7) * 4;
            float4 v = *(const float4*)(X + (size_t)(mBase + r) * 256 + kc + c);
            As[r][c + 0] = to_tf32(v.x); As[r][c + 1] = to_tf32(v.y);
            As[r][c + 2] = to_tf32(v.z); As[r][c + 3] = to_tf32(v.w);
            float4 w4 = *(const float4*)(W + (size_t)(nBase + r) * 256 + kc + c);
            Bs[r][c + 0] = to_tf32(w4.x); Bs[r][c + 1] = to_tf32(w4.y);
            Bs[r][c + 2] = to_tf32(w4.z); Bs[r][c + 3] = to_tf32(w4.w);
        }
        __syncthreads();

#pragma unroll
        for (int ko = 0; ko < 32; ko += 8) {
            uint32_t a[4][4], bb[4][2];
#pragma unroll
            for (int mi = 0; mi < 4; mi++) {
                int row = wm + mi * 16 + g;
                a[mi][0] = __float_as_uint(As[row][ko + t]);
                a[mi][1] = __float_as_uint(As[row + 8][ko + t]);
                a[mi][2] = __float_as_uint(As[row][ko + t + 4]);
                a[mi][3] = __float_as_uint(As[row + 8][ko + t + 4]);
            }
#pragma unroll
            for (int ni = 0; ni < 4; ni++) {
                int col = wn + ni * 8 + g;
                bb[ni][0] = __float_as_uint(Bs[col][ko + t]);
                bb[ni][1] = __float_as_uint(Bs[col][ko + t + 4]);
            }
#pragma unroll
            for (int mi = 0; mi < 4; mi++)
#pragma unroll
                for (int ni = 0; ni < 4; ni++)
                    mma_tf32(acc[mi][ni], a[mi], bb[ni]);
        }
        __syncthreads();
    }

    const float qscale = 0.17677669529663687f;  // 32^-0.5
#pragma unroll
    for (int mi = 0; mi < 4; mi++) {
#pragma unroll
        for (int ni = 0; ni < 4; ni++) {
            int gn = nBase + wn + ni * 8 + t * 2;
            float bv0 = bias[gn], bv1 = bias[gn + 1];
            if (QKV_MODE) {
                int which = gn >> 8;          // 0:q 1:k 2:v
                int h = (gn >> 5) & 7;
                int d = gn & 31;
                float sc = (which == 0) ? qscale : 1.0f;
#pragma unroll
                for (int half = 0; half < 2; half++) {
                    int gm = mBase + wm + mi * 16 + g + half * 8;
                    int b = gm / 49;
                    int r = gm - b * 49;
                    float v0 = (acc[mi][ni][half * 2 + 0] + bv0) * sc;
                    float v1 = (acc[mi][ni][half * 2 + 1] + bv1) * sc;
                    size_t off = ((((size_t)b * 8 + h) * 3 + which) * 49 + r) * 32 + d;
                    *(float2*)(g_qkv + off) = make_float2(v0, v1);
                }
            } else {
#pragma unroll
                for (int half = 0; half < 2; half++) {
                    int gm = mBase + wm + mi * 16 + g + half * 8;
                    float v0 = acc[mi][ni][half * 2 + 0] + bv0;
                    float v1 = acc[mi][ni][half * 2 + 1] + bv1;
                    *(float2*)(out + (size_t)gm * 256 + gn) = make_float2(v0, v1);
                }
            }
        }
    }
}

// ---------------------------------------------------------------------------
// Tensor-core attention.
// grid = 8192 (window b = blockIdx>>1, heads h0..h0+3 where h0=(blockIdx&1)*4)
// 8 warps: warp = head_local*2 + mhalf; mhalf picks rows 0-31 / 32-63 of the
// 64-padded S. S and PV via m16n8k8 tf32 mma; softmax in accumulators.
// ---------------------------------------------------------------------------
// smem float offsets
#define AQ_OFF  0                         // q [4][64][36]  (rows 49-63 zero)
#define AK_OFF  9216                      // k [4][56][36]  (rows 49-55 zero)
#define AV_OFF  17280                     // vT [4][32][60] (cols 49-59 zero)
#define AS_OFF  24960                     // P  [8 warps][32][60]
#define AM_OFF  40320                     // mask [49][52]
#define AB_OFF  42868                     // bt [169*8]
#define AT_FLOATS 44220
#define AT_SMEM (AT_FLOATS * 4)           // 176880 B

__global__ __launch_bounds__(256) void attn_mma_kernel(
    const float* __restrict__ mask, const float* __restrict__ bt)
{
    extern __shared__ float sm[];
    float* q_s  = sm + AQ_OFF;
    float* k_s  = sm + AK_OFF;
    float* vT_s = sm + AV_OFF;
    float* sS   = sm + AS_OFF;
    float* mk_s = sm + AM_OFF;
    float* bt_s = sm + AB_OFF;

    const int tid = threadIdx.x;
    const int b   = blockIdx.x >> 1;
    const int h0  = (blockIdx.x & 1) * 4;

    // zero q/k/vT (covers all pad regions): floats [0, 24960) = 6240 float4
    for (int idx = tid; idx < 6240; idx += 256)
        ((float4*)sm)[idx] = make_float4(0.f, 0.f, 0.f, 0.f);
    __syncthreads();

    const float* gbase = g_qkv + ((size_t)b * 8 + h0) * 3 * 1568;

    // q (tf32): [hl][i][d] stride 36
    for (int idx = tid; idx < 1568; idx += 256) {
        int hl = idx / 392, r = idx - hl * 392;
        float4 v = *(const float4*)(gbase + (size_t)(hl * 3 + 0) * 1568 + r * 4);
        int i = r >> 3, d0 = (r & 7) * 4;
        float* dst = q_s + (hl * 64 + i) * 36 + d0;
        dst[0] = to_tf32(v.x); dst[1] = to_tf32(v.y);
        dst[2] = to_tf32(v.z); dst[3] = to_tf32(v.w);
    }
    // k (tf32): [hl][j][d] stride 36
    for (int idx = tid; idx < 1568; idx += 256) {
        int hl = idx / 392, r = idx - hl * 392;
        float4 v = *(const float4*)(gbase + (size_t)(hl * 3 + 1) * 1568 + r * 4);
        int j = r >> 3, d0 = (r & 7) * 4;
        float* dst = k_s + (hl * 56 + j) * 36 + d0;
        dst[0] = to_tf32(v.x); dst[1] = to_tf32(v.y);
        dst[2] = to_tf32(v.z); dst[3] = to_tf32(v.w);
    }
    // v transposed (tf32): [hl][d][j] stride 60
    for (int idx = tid; idx < 1568; idx += 256) {
        int hl = idx / 392, r = idx - hl * 392;
        float4 v = *(const float4*)(gbase + (size_t)(hl * 3 + 2) * 1568 + r * 4);
        int j = r >> 3, d0 = (r & 7) * 4;
        float* dst = vT_s + hl * 32 * 60;
        dst[(d0 + 0) * 60 + j] = to_tf32(v.x);
        dst[(d0 + 1) * 60 + j] = to_tf32(v.y);
        dst[(d0 + 2) * 60 + j] = to_tf32(v.z);
        dst[(d0 + 3) * 60 + j] = to_tf32(v.w);
    }
    // mask window [49][52]
    {
        const float* mw = mask + (size_t)(b & 63) * 2401;
        for (int idx = tid; idx < 2401; idx += 256) {
            int i = idx / 49, j = idx - i * 49;
            mk_s[i * 52 + j] = mw[idx];
        }
    }
    for (int idx = tid; idx < 1352; idx += 256) bt_s[idx] = bt[idx];
    __syncthreads();

    const int warp = tid >> 5, lane = tid & 31;
    const int hl = warp >> 1;          // head local 0..3
    const int h  = h0 + hl;            // global head
    const int mhalf = warp & 1;        // row half: 0-31 or 32-63
    const int g = lane >> 2, t = lane & 3;

    const float* q_h  = q_s + (hl * 64 + mhalf * 32) * 36;
    const float* k_h  = k_s + hl * 56 * 36;
    const float* vt_h = vT_s + hl * 32 * 60;
    float* sS_w = sS + warp * 32 * 60;

    // ---- S = q @ k^T  : acc[2 m-tiles][7 j-tiles][4] ----
    float acc[2][7][4] = {};
#pragma unroll
    for (int kc = 0; kc < 4; kc++) {          // d in chunks of 8
        uint32_t a[2][4];
#pragma unroll
        for (int mt = 0; mt < 2; mt++) {
            const float* qr = q_h + (mt * 16 + g) * 36 + kc * 8;
            a[mt][0] = __float_as_uint(qr[t]);
            a[mt][1] = __float_as_uint(qr[8 * 36 + t]);
            a[mt][2] = __float_as_uint(qr[t + 4]);
            a[mt][3] = __float_as_uint(qr[8 * 36 + t + 4]);
        }
#pragma unroll
        for (int tj = 0; tj < 7; tj++) {
            uint32_t bb[2];
            const float* kr = k_h + (tj * 8 + g) * 36 + kc * 8;
            bb[0] = __float_as_uint(kr[t]);
            bb[1] = __float_as_uint(kr[t + 4]);
            mma_tf32(acc[0][tj], a[0], bb);
            mma_tf32(acc[1][tj], a[1], bb);
        }
    }

    // ---- bias + mask + softmax (per row slot), P -> sS_w (tf32) ----
#pragma unroll
    for (int mt = 0; mt < 2; mt++) {
#pragma unroll
        for (int rh = 0; rh < 2; rh++) {
            int irow = mhalf * 32 + mt * 16 + g + rh * 8;
            bool vi = (irow < 49);
            int ri = irow / 7, ci = irow - ri * 7;
            float vals[14];
#pragma unroll
            for (int tj = 0; tj < 7; tj++) {
#pragma unroll
                for (int cc = 0; cc < 2; cc++) {
                    int j = tj * 8 + 2 * t + cc;
                    float s = acc[mt][tj][rh * 2 + cc];
                    if (vi && j < 49) {
                        int rj = j / 7, cj = j - rj * 7;
                        int bidx = (ri - rj + 6) * 13 + (ci - cj + 6);
                        s += bt_s[bidx * 8 + h] + mk_s[irow * 52 + j];
                    } else {
                        s = -1e30f;
                    }
                    vals[tj * 2 + cc] = s;
                }
            }
            float m = vals[0];
#pragma unroll
            for (int u = 1; u < 14; u++) m = fmaxf(m, vals[u]);
            m = fmaxf(m, __shfl_xor_sync(0xffffffffu, m, 1));
            m = fmaxf(m, __shfl_xor_sync(0xffffffffu, m, 2));
            float ssum = 0.f;
#pragma unroll
            for (int u = 0; u < 14; u++) { vals[u] = __expf(vals[u] - m); ssum += vals[u]; }
            ssum += __shfl_xor_sync(0xffffffffu, ssum, 1);
            ssum += __shfl_xor_sync(0xffffffffu, ssum, 2);
            float inv = __frcp_rn(ssum);
            float* prow = sS_w + (mt * 16 + g + rh * 8) * 60;
#pragma unroll
            for (int tj = 0; tj < 7; tj++) {
                float2 p2 = make_float2(to_tf32(vals[tj * 2] * inv),
                                        to_tf32(vals[tj * 2 + 1] * inv));
                *(float2*)(prow + tj * 8 + 2 * t) = p2;
            }
        }
    }
    __syncwarp();

    // ---- out = P @ v : pacc[2 m-tiles][4 d-tiles][4] ----
    float pacc[2][4][4] = {};
#pragma unroll
    for (int kc = 0; kc < 7; kc++) {          // j in chunks of 8
        uint32_t a[2][4];
#pragma unroll
        for (int mt = 0; mt < 2; mt++) {
            const float* pr = sS_w + (mt * 16 + g) * 60 + kc * 8;
            a[mt][0] = __float_as_uint(pr[t]);
            a[mt][1] = __float_as_uint(pr[8 * 60 + t]);
            a[mt][2] = __float_as_uint(pr[t + 4]);
            a[mt][3] = __float_as_uint(pr[8 * 60 + t + 4]);
        }
#pragma unroll
        for (int nt = 0; nt < 4; nt++) {
            uint32_t bb[2];
            const float* vr = vt_h + (nt * 8 + g) * 60 + kc * 8;
            bb[0] = __float_as_uint(vr[t]);
            bb[1] = __float_as_uint(vr[t + 4]);
            mma_tf32(pacc[0][nt], a[0], bb);
            mma_tf32(pacc[1][nt], a[1], bb);
        }
    }

    // ---- store rows i < 49 ----
#pragma unroll
    for (int mt = 0; mt < 2; mt++) {
#pragma unroll
        for (int rh = 0; rh < 2; rh++) {
            int irow = mhalf * 32 + mt * 16 + g + rh * 8;
            if (irow < 49) {
                float* op = g_attn + ((size_t)b * 49 + irow) * 256 + h * 32;
#pragma unroll
                for (int nt = 0; nt < 4; nt++) {
                    int d = nt * 8 + 2 * t;
                    *(float2*)(op + d) = make_float2(pacc[mt][nt][rh * 2 + 0],
                                                     pacc[mt][nt][rh * 2 + 1]);
                }
            }
        }
    }
}

// ---------------------------------------------------------------------------
extern "C" void kernel_launch(void* const* d_in, const int* in_sizes, int n_in,
                              void* d_out, int out_size)
{
    const float* x      = (const float*)d_in[0];
    const float* mask   = (const float*)d_in[1];
    const float* qkv_w  = (const float*)d_in[2];
    const float* qkv_b  = (const float*)d_in[3];
    const float* proj_w = (const float*)d_in[4];
    const float* proj_b = (const float*)d_in[5];
    const float* bt     = (const float*)d_in[6];
    float* out = (float*)d_out;

    cudaFuncSetAttribute((const void*)attn_mma_kernel,
                         cudaFuncAttributeMaxDynamicSharedMemorySize, AT_SMEM);

    gemm128<true><<<dim3(M_ROWS / 128, 6), 256>>>(x, qkv_w, qkv_b, nullptr);
    attn_mma_kernel<<<B_WIN * 2, 256, AT_SMEM>>>(mask, bt);
    gemm128<false><<<dim3(M_ROWS / 128, 2), 256>>>(nullptr, proj_w, proj_b, out);
}

// round 6
// speedup vs baseline: 1.5265x; 1.5265x over previous
#include <cuda_runtime.h>
#include <cstdint>

#define N_TOK   49
#define C_DIM   256
#define H_NUM   8
#define HD      32
#define B_WIN   4096
#define M_ROWS  (B_WIN * N_TOK)   // 200704

// Scratch (allocation-free rule: __device__ globals)
__device__ float g_qkv[(size_t)B_WIN * H_NUM * 3 * N_TOK * HD];   // 616 MB
__device__ float g_attn[(size_t)M_ROWS * C_DIM];                  // 205 MB
__device__ float g_bm[512 * 2401];                                // bias+mask, 4.9 MB

// ---------------------------------------------------------------------------
__device__ __forceinline__ float to_tf32(float x) {
    uint32_t u;
    asm("cvt.rna.tf32.f32 %0, %1;" : "=r"(u) : "f"(x));
    return __uint_as_float(u);
}

__device__ __forceinline__ void mma_tf32(float c[4], const uint32_t a[4], const uint32_t b[2]) {
    asm volatile(
        "mma.sync.aligned.m16n8k8.row.col.f32.tf32.tf32.f32 "
        "{%0,%1,%2,%3}, {%4,%5,%6,%7}, {%8,%9}, {%0,%1,%2,%3};"
        : "+f"(c[0]), "+f"(c[1]), "+f"(c[2]), "+f"(c[3])
        : "r"(a[0]), "r"(a[1]), "r"(a[2]), "r"(a[3]), "r"(b[0]), "r"(b[1]));
}

// ---------------------------------------------------------------------------
// GEMM: CTA tile 128x128, warp tile 64x32 (8 warps: 2 along M x 4 along N).
// (unchanged from R5 — proven: qkv 729us, proj ~243us)
// ---------------------------------------------------------------------------
template<bool QKV_MODE>
__global__ __launch_bounds__(256) void gemm128(
    const float* __restrict__ Xin, const float* __restrict__ W,
    const float* __restrict__ bias, float* __restrict__ out)
{
    __shared__ float As[128][36];
    __shared__ float Bs[128][36];
    const int tid = threadIdx.x;
    const int mBase = blockIdx.x * 128;
    const int nBase = blockIdx.y * 128;
    const float* X = QKV_MODE ? Xin : (const float*)g_attn;

    const int warp = tid >> 5, lane = tid & 31;
    const int wm = (warp & 1) * 64, wn = (warp >> 1) * 32;
    const int g = lane >> 2, t = lane & 3;

    float acc[4][4][4] = {};

    for (int kc = 0; kc < 256; kc += 32) {
#pragma unroll
        for (int p = 0; p < 4; p++) {
            int idx = tid + p * 256;
            int r = idx >> 3, c = (idx & 7) * 4;
            float4 v = *(const float4*)(X + (size_t)(mBase + r) * 256 + kc + c);
            As[r][c + 0] = to_tf32(v.x); As[r][c + 1] = to_tf32(v.y);
            As[r][c + 2] = to_tf32(v.z); As[r][c + 3] = to_tf32(v.w);
            float4 w4 = *(const float4*)(W + (size_t)(nBase + r) * 256 + kc + c);
            Bs[r][c + 0] = to_tf32(w4.x); Bs[r][c + 1] = to_tf32(w4.y);
            Bs[r][c + 2] = to_tf32(w4.z); Bs[r][c + 3] = to_tf32(w4.w);
        }
        __syncthreads();

#pragma unroll
        for (int ko = 0; ko < 32; ko += 8) {
            uint32_t a[4][4], bb[4][2];
#pragma unroll
            for (int mi = 0; mi < 4; mi++) {
                int row = wm + mi * 16 + g;
                a[mi][0] = __float_as_uint(As[row][ko + t]);
                a[mi][1] = __float_as_uint(As[row + 8][ko + t]);
                a[mi][2] = __float_as_uint(As[row][ko + t + 4]);
                a[mi][3] = __float_as_uint(As[row + 8][ko + t + 4]);
            }
#pragma unroll
            for (int ni = 0; ni < 4; ni++) {
                int col = wn + ni * 8 + g;
                bb[ni][0] = __float_as_uint(Bs[col][ko + t]);
                bb[ni][1] = __float_as_uint(Bs[col][ko + t + 4]);
            }
#pragma unroll
            for (int mi = 0; mi < 4; mi++)
#pragma unroll
                for (int ni = 0; ni < 4; ni++)
                    mma_tf32(acc[mi][ni], a[mi], bb[ni]);
        }
        __syncthreads();
    }

    const float qscale = 0.17677669529663687f;
#pragma unroll
    for (int mi = 0; mi < 4; mi++) {
#pragma unroll
        for (int ni = 0; ni < 4; ni++) {
            int gn = nBase + wn + ni * 8 + t * 2;
            float bv0 = bias[gn], bv1 = bias[gn + 1];
            if (QKV_MODE) {
                int which = gn >> 8;
                int h = (gn >> 5) & 7;
                int d = gn & 31;
                float sc = (which == 0) ? qscale : 1.0f;
#pragma unroll
                for (int half = 0; half < 2; half++) {
                    int gm = mBase + wm + mi * 16 + g + half * 8;
                    int b = gm / 49;
                    int r = gm - b * 49;
                    float v0 = (acc[mi][ni][half * 2 + 0] + bv0) * sc;
                    float v1 = (acc[mi][ni][half * 2 + 1] + bv1) * sc;
                    size_t off = ((((size_t)b * 8 + h) * 3 + which) * 49 + r) * 32 + d;
                    *(float2*)(g_qkv + off) = make_float2(v0, v1);
                }
            } else {
#pragma unroll
                for (int half = 0; half < 2; half++) {
                    int gm = mBase + wm + mi * 16 + g + half * 8;
                    float v0 = acc[mi][ni][half * 2 + 0] + bv0;
                    float v1 = acc[mi][ni][half * 2 + 1] + bv1;
                    *(float2*)(out + (size_t)gm * 256 + gn) = make_float2(v0, v1);
                }
            }
        }
    }
}

// ---------------------------------------------------------------------------
// Kernel 0: fuse bias_table + mask -> g_bm[(w*8+h)][i*49+j]
// ---------------------------------------------------------------------------
__global__ __launch_bounds__(256) void fuse_bm_kernel(
    const float* __restrict__ mask, const float* __restrict__ bt)
{
    const int wh = blockIdx.x;          // 0..511
    const int w = wh >> 3, h = wh & 7;
    const float* mw = mask + (size_t)w * 2401;
    float* dst = g_bm + (size_t)wh * 2401;
    for (int idx = threadIdx.x; idx < 2401; idx += 256) {
        int i = idx / 49, j = idx - i * 49;
        int ri = i / 7, ci = i - ri * 7;
        int rj = j / 7, cj = j - rj * 7;
        int bidx = (ri - rj + 6) * 13 + (ci - cj + 6);
        dst[idx] = mw[idx] + bt[bidx * 8 + h];
    }
}

// ---------------------------------------------------------------------------
// Slim tensor-core attention: grid = 32768 (one CTA per (window, head)),
// block = 64 (2 warps = row halves 0-31 / 32-63 of the 64-padded S).
// q/k/v fragments loaded lane-directly from gmem (no staging); smem only
// holds P for re-fragmenting. No __syncthreads at all.
// ---------------------------------------------------------------------------
__global__ __launch_bounds__(64) void attn_slim_kernel()
{
    __shared__ float sP[2 * 32 * 60];   // per-warp P tiles, stride 60

    const int bh   = blockIdx.x;
    const int b    = bh >> 3;
    const int h    = bh & 7;
    const int warp = threadIdx.x >> 5;  // row half
    const int lane = threadIdx.x & 31;
    const int g = lane >> 2, t = lane & 3;

    const float* qb = g_qkv + (size_t)bh * 3 * 1568;          // q [49][32]
    const float* kb = qb + 1568;                              // k [49][32]
    const float* vb = qb + 2 * 1568;                          // v [49][32]

    // ---- S = q @ k^T : acc[2 m-tiles][7 j-tiles][4] ----
    float acc[2][7][4] = {};
#pragma unroll
    for (int kc = 0; kc < 4; kc++) {           // d chunks of 8
        uint32_t a[2][4];
#pragma unroll
        for (int mt = 0; mt < 2; mt++) {
            const float* qr = qb + (warp * 32 + mt * 16 + g) * 32 + kc * 8;
            a[mt][0] = __float_as_uint(to_tf32(qr[t]));
            a[mt][1] = __float_as_uint(to_tf32(qr[8 * 32 + t]));
            a[mt][2] = __float_as_uint(to_tf32(qr[t + 4]));
            a[mt][3] = __float_as_uint(to_tf32(qr[8 * 32 + t + 4]));
        }
#pragma unroll
        for (int tj = 0; tj < 7; tj++) {
            const float* kr = kb + (tj * 8 + g) * 32 + kc * 8;
            uint32_t bb[2];
            bb[0] = __float_as_uint(to_tf32(kr[t]));
            bb[1] = __float_as_uint(to_tf32(kr[t + 4]));
            mma_tf32(acc[0][tj], a[0], bb);
            mma_tf32(acc[1][tj], a[1], bb);
        }
    }

    // ---- softmax with fused bias+mask, P -> sP (tf32) ----
    const float* bmp = g_bm + ((size_t)((b & 63) * 8 + h)) * 2401;
    float* sP_w = sP + warp * 32 * 60;
#pragma unroll
    for (int mt = 0; mt < 2; mt++) {
#pragma unroll
        for (int rh = 0; rh < 2; rh++) {
            int irow = warp * 32 + mt * 16 + g + rh * 8;
            bool vi = (irow < 49);
            const float* bmr = bmp + irow * 49;
            float vals[14];
#pragma unroll
            for (int tj = 0; tj < 7; tj++) {
#pragma unroll
                for (int cc = 0; cc < 2; cc++) {
                    int j = tj * 8 + 2 * t + cc;
                    float s = acc[mt][tj][rh * 2 + cc];
                    s = (vi && j < 49) ? (s + bmr[j]) : -1e30f;
                    vals[tj * 2 + cc] = s;
                }
            }
            float m = vals[0];
#pragma unroll
            for (int u = 1; u < 14; u++) m = fmaxf(m, vals[u]);
            m = fmaxf(m, __shfl_xor_sync(0xffffffffu, m, 1));
            m = fmaxf(m, __shfl_xor_sync(0xffffffffu, m, 2));
            float ssum = 0.f;
#pragma unroll
            for (int u = 0; u < 14; u++) { vals[u] = __expf(vals[u] - m); ssum += vals[u]; }
            ssum += __shfl_xor_sync(0xffffffffu, ssum, 1);
            ssum += __shfl_xor_sync(0xffffffffu, ssum, 2);
            float inv = __frcp_rn(ssum);
            float* prow = sP_w + (mt * 16 + g + rh * 8) * 60;
#pragma unroll
            for (int tj = 0; tj < 7; tj++) {
                float2 p2 = make_float2(to_tf32(vals[tj * 2] * inv),
                                        to_tf32(vals[tj * 2 + 1] * inv));
                *(float2*)(prow + tj * 8 + 2 * t) = p2;
            }
        }
    }
    __syncwarp();

    // ---- out = P @ v : pacc[2][4][4]; v fragments direct from gmem ----
    float pacc[2][4][4] = {};
#pragma unroll
    for (int kc = 0; kc < 7; kc++) {           // j chunks of 8
        uint32_t a[2][4];
#pragma unroll
        for (int mt = 0; mt < 2; mt++) {
            const float* pr = sP_w + (mt * 16 + g) * 60 + kc * 8;
            a[mt][0] = __float_as_uint(pr[t]);
            a[mt][1] = __float_as_uint(pr[8 * 60 + t]);
            a[mt][2] = __float_as_uint(pr[t + 4]);
            a[mt][3] = __float_as_uint(pr[8 * 60 + t + 4]);
        }
        int j0 = kc * 8 + t;
        int j1 = kc * 8 + t + 4;
#pragma unroll
        for (int nt = 0; nt < 4; nt++) {
            int d = nt * 8 + g;
            uint32_t bb[2];
            bb[0] = (j0 < 49) ? __float_as_uint(to_tf32(vb[j0 * 32 + d])) : 0u;
            bb[1] = (j1 < 49) ? __float_as_uint(to_tf32(vb[j1 * 32 + d])) : 0u;
            mma_tf32(pacc[0][nt], a[0], bb);
            mma_tf32(pacc[1][nt], a[1], bb);
        }
    }

    // ---- store rows i < 49 ----
#pragma unroll
    for (int mt = 0; mt < 2; mt++) {
#pragma unroll
        for (int rh = 0; rh < 2; rh++) {
            int irow = warp * 32 + mt * 16 + g + rh * 8;
            if (irow < 49) {
                float* op = g_attn + ((size_t)b * 49 + irow) * 256 + h * 32;
#pragma unroll
                for (int nt = 0; nt < 4; nt++) {
                    int d = nt * 8 + 2 * t;
                    *(float2*)(op + d) = make_float2(pacc[mt][nt][rh * 2 + 0],
                                                     pacc[mt][nt][rh * 2 + 1]);
                }
            }
        }
    }
}

// ---------------------------------------------------------------------------
extern "C" void kernel_launch(void* const* d_in, const int* in_sizes, int n_in,
                              void* d_out, int out_size)
{
    const float* x      = (const float*)d_in[0];
    const float* mask   = (const float*)d_in[1];
    const float* qkv_w  = (const float*)d_in[2];
    const float* qkv_b  = (const float*)d_in[3];
    const float* proj_w = (const float*)d_in[4];
    const float* proj_b = (const float*)d_in[5];
    const float* bt     = (const float*)d_in[6];
    float* out = (float*)d_out;

    fuse_bm_kernel<<<512, 256>>>(mask, bt);
    gemm128<true><<<dim3(M_ROWS / 128, 6), 256>>>(x, qkv_w, qkv_b, nullptr);
    attn_slim_kernel<<<B_WIN * H_NUM, 64>>>();
    gemm128<false><<<dim3(M_ROWS / 128, 2), 256>>>(nullptr, proj_w, proj_b, out);
}

// round 8
// speedup vs baseline: 1.6558x; 1.0848x over previous
#include <cuda_runtime.h>
#include <cstdint>

#define N_TOK   49
#define C_DIM   256
#define H_NUM   8
#define HD      32
#define B_WIN   4096
#define M_ROWS  (B_WIN * N_TOK)   // 200704

// Scratch (allocation-free rule: __device__ globals)
__device__ float g_qkv[(size_t)B_WIN * H_NUM * 3 * N_TOK * HD];   // 616 MB
__device__ float g_attn[(size_t)M_ROWS * C_DIM];                  // 205 MB (tf32-rounded)
__device__ float g_xcvt[(size_t)M_ROWS * C_DIM];                  // 205 MB (tf32-rounded x)
__device__ float g_wq[768 * 256];                                 // tf32-rounded qkv_w
__device__ float g_wp[256 * 256];                                 // tf32-rounded proj_w
__device__ float g_bm[512 * 2401];                                // bias+mask, 4.9 MB

// ---------------------------------------------------------------------------
__device__ __forceinline__ float to_tf32(float x) {
    uint32_t u;
    asm("cvt.rna.tf32.f32 %0, %1;" : "=r"(u) : "f"(x));
    return __uint_as_float(u);
}

__device__ __forceinline__ void mma_tf32(float c[4], const uint32_t a[4], const uint32_t b[2]) {
    asm volatile(
        "mma.sync.aligned.m16n8k8.row.col.f32.tf32.tf32.f32 "
        "{%0,%1,%2,%3}, {%4,%5,%6,%7}, {%8,%9}, {%0,%1,%2,%3};"
        : "+f"(c[0]), "+f"(c[1]), "+f"(c[2]), "+f"(c[3])
        : "r"(a[0]), "r"(a[1]), "r"(a[2]), "r"(a[3]), "r"(b[0]), "r"(b[1]));
}

__device__ __forceinline__ void cp16(uint32_t smem_addr, const float* gptr) {
    asm volatile("cp.async.cg.shared.global [%0], [%1], 16;"
                 :: "r"(smem_addr), "l"(gptr) : "memory");
}
__device__ __forceinline__ void cp_commit() {
    asm volatile("cp.async.commit_group;" ::: "memory");
}
template<int N>
__device__ __forceinline__ void cp_wait() {
    asm volatile("cp.async.wait_group %0;" :: "n"(N) : "memory");
}

// ---------------------------------------------------------------------------
// Kernel A: tf32 pre-convert (grid-stride over float4)
//   which: 0 -> g_xcvt, 1 -> g_wq, 2 -> g_wp
// ---------------------------------------------------------------------------
__global__ __launch_bounds__(256) void cvt_tf32_kernel(
    const float* __restrict__ src, int n4, int which)
{
    float* dst = (which == 0) ? g_xcvt : (which == 1) ? g_wq : g_wp;
    int idx = blockIdx.x * blockDim.x + threadIdx.x;
    int stride = gridDim.x * blockDim.x;
    for (; idx < n4; idx += stride) {
        float4 v = ((const float4*)src)[idx];
        v.x = to_tf32(v.x); v.y = to_tf32(v.y);
        v.z = to_tf32(v.z); v.w = to_tf32(v.w);
        ((float4*)dst)[idx] = v;
    }
}

// ---------------------------------------------------------------------------
// GEMM: CTA tile 128x128, warp tile 64x32, cp.async double-buffered slabs.
// Inputs are pre-converted to tf32 (g_xcvt/g_wq or g_attn/g_wp).
// dynamic smem: 2 * (128*36 A + 128*36 B) * 4 = 73728 B
// ---------------------------------------------------------------------------
#define SLAB_FLOATS (128 * 36)
#define GEMM_CA_SMEM (4 * SLAB_FLOATS * 4)

template<bool QKV_MODE>
__global__ __launch_bounds__(256) void gemm128_ca(
    const float* __restrict__ bias, float* __restrict__ out)
{
    extern __shared__ float sm[];
    // layout: As[0], As[1], Bs[0], Bs[1] each SLAB_FLOATS
    const uint32_t sm_u32 = (uint32_t)__cvta_generic_to_shared(sm);

    const int tid = threadIdx.x;
    const int mBase = blockIdx.x * 128;
    const int nBase = blockIdx.y * 128;
    const float* X = QKV_MODE ? g_xcvt : g_attn;
    const float* W = QKV_MODE ? g_wq : g_wp;

    const int warp = tid >> 5, lane = tid & 31;
    const int wm = (warp & 1) * 64, wn = (warp >> 1) * 32;
    const int g = lane >> 2, t = lane & 3;

    // staging coords (per thread): rows r0+{0,32,64,96}, cols c0..c0+3
    const int r0 = tid >> 3;
    const int c0 = (tid & 7) * 4;

    // issue slab ks into buffer buf
    auto issue = [&](int ks, int buf) {
        const float* xrow = X + (size_t)(mBase + r0) * 256 + ks * 32 + c0;
        const float* wrow = W + (size_t)(nBase + r0) * 256 + ks * 32 + c0;
        uint32_t adstA = sm_u32 + (uint32_t)((buf * SLAB_FLOATS + r0 * 36 + c0) * 4);
        uint32_t adstB = sm_u32 + (uint32_t)((2 * SLAB_FLOATS + buf * SLAB_FLOATS + r0 * 36 + c0) * 4);
#pragma unroll
        for (int p = 0; p < 4; p++) {
            cp16(adstA + p * 32 * 36 * 4, xrow + (size_t)p * 32 * 256);
            cp16(adstB + p * 32 * 36 * 4, wrow + (size_t)p * 32 * 256);
        }
        cp_commit();
    };

    float acc[4][4][4] = {};

    issue(0, 0);
    for (int ks = 0; ks < 8; ks++) {
        const int buf = ks & 1;
        if (ks < 7) issue(ks + 1, buf ^ 1);
        if (ks < 7) cp_wait<1>(); else cp_wait<0>();
        __syncthreads();

        const float* As = sm + buf * SLAB_FLOATS;
        const float* Bs = sm + 2 * SLAB_FLOATS + buf * SLAB_FLOATS;

#pragma unroll
        for (int ko = 0; ko < 32; ko += 8) {
            uint32_t a[4][4], bb[4][2];
#pragma unroll
            for (int mi = 0; mi < 4; mi++) {
                int row = wm + mi * 16 + g;
                a[mi][0] = __float_as_uint(As[row * 36 + ko + t]);
                a[mi][1] = __float_as_uint(As[(row + 8) * 36 + ko + t]);
                a[mi][2] = __float_as_uint(As[row * 36 + ko + t + 4]);
                a[mi][3] = __float_as_uint(As[(row + 8) * 36 + ko + t + 4]);
            }
#pragma unroll
            for (int ni = 0; ni < 4; ni++) {
                int col = wn + ni * 8 + g;
                bb[ni][0] = __float_as_uint(Bs[col * 36 + ko + t]);
                bb[ni][1] = __float_as_uint(Bs[col * 36 + ko + t + 4]);
            }
#pragma unroll
            for (int mi = 0; mi < 4; mi++)
#pragma unroll
                for (int ni = 0; ni < 4; ni++)
                    mma_tf32(acc[mi][ni], a[mi], bb[ni]);
        }
        __syncthreads();   // all warps done reading buf before it is re-issued
    }

    const float qscale = 0.17677669529663687f;
#pragma unroll
    for (int mi = 0; mi < 4; mi++) {
#pragma unroll
        for (int ni = 0; ni < 4; ni++) {
            int gn = nBase + wn + ni * 8 + t * 2;
            float bv0 = bias[gn], bv1 = bias[gn + 1];
            if (QKV_MODE) {
                int which = gn >> 8;
                int h = (gn >> 5) & 7;
                int d = gn & 31;
                float sc = (which == 0) ? qscale : 1.0f;
#pragma unroll
                for (int half = 0; half < 2; half++) {
                    int gm = mBase + wm + mi * 16 + g + half * 8;
                    int b = gm / 49;
                    int r = gm - b * 49;
                    float v0 = (acc[mi][ni][half * 2 + 0] + bv0) * sc;
                    float v1 = (acc[mi][ni][half * 2 + 1] + bv1) * sc;
                    size_t off = ((((size_t)b * 8 + h) * 3 + which) * 49 + r) * 32 + d;
                    *(float2*)(g_qkv + off) = make_float2(v0, v1);
                }
            } else {
#pragma unroll
                for (int half = 0; half < 2; half++) {
                    int gm = mBase + wm + mi * 16 + g + half * 8;
                    float v0 = acc[mi][ni][half * 2 + 0] + bv0;
                    float v1 = acc[mi][ni][half * 2 + 1] + bv1;
                    *(float2*)(out + (size_t)gm * 256 + gn) = make_float2(v0, v1);
                }
            }
        }
    }
}

// ---------------------------------------------------------------------------
// Kernel 0: fuse bias_table + mask -> g_bm[(w*8+h)][i*49+j]
// ---------------------------------------------------------------------------
__global__ __launch_bounds__(256) void fuse_bm_kernel(
    const float* __restrict__ mask, const float* __restrict__ bt)
{
    const int wh = blockIdx.x;          // 0..511
    const int w = wh >> 3, h = wh & 7;
    const float* mw = mask + (size_t)w * 2401;
    float* dst = g_bm + (size_t)wh * 2401;
    for (int idx = threadIdx.x; idx < 2401; idx += 256) {
        int i = idx / 49, j = idx - i * 49;
        int ri = i / 7, ci = i - ri * 7;
        int rj = j / 7, cj = j - rj * 7;
        int bidx = (ri - rj + 6) * 13 + (ci - cj + 6);
        dst[idx] = mw[idx] + bt[bidx * 8 + h];
    }
}

// ---------------------------------------------------------------------------
// Slim tensor-core attention (R6, proven ~350us): one CTA per (window, head),
// 64 threads. Output stored tf32-rounded so proj can consume it directly.
// ---------------------------------------------------------------------------
__global__ __launch_bounds__(64) void attn_slim_kernel()
{
    __shared__ float sP[2 * 32 * 60];

    const int bh   = blockIdx.x;
    const int b    = bh >> 3;
    const int h    = bh & 7;
    const int warp = threadIdx.x >> 5;
    const int lane = threadIdx.x & 31;
    const int g = lane >> 2, t = lane & 3;

    const float* qb = g_qkv + (size_t)bh * 3 * 1568;
    const float* kb = qb + 1568;
    const float* vb = qb + 2 * 1568;

    float acc[2][7][4] = {};
#pragma unroll
    for (int kc = 0; kc < 4; kc++) {
        uint32_t a[2][4];
#pragma unroll
        for (int mt = 0; mt < 2; mt++) {
            const float* qr = qb + (warp * 32 + mt * 16 + g) * 32 + kc * 8;
            a[mt][0] = __float_as_uint(to_tf32(qr[t]));
            a[mt][1] = __float_as_uint(to_tf32(qr[8 * 32 + t]));
            a[mt][2] = __float_as_uint(to_tf32(qr[t + 4]));
            a[mt][3] = __float_as_uint(to_tf32(qr[8 * 32 + t + 4]));
        }
#pragma unroll
        for (int tj = 0; tj < 7; tj++) {
            const float* kr = kb + (tj * 8 + g) * 32 + kc * 8;
            uint32_t bb[2];
            bb[0] = __float_as_uint(to_tf32(kr[t]));
            bb[1] = __float_as_uint(to_tf32(kr[t + 4]));
            mma_tf32(acc[0][tj], a[0], bb);
            mma_tf32(acc[1][tj], a[1], bb);
        }
    }

    const float* bmp = g_bm + ((size_t)((b & 63) * 8 + h)) * 2401;
    float* sP_w = sP + warp * 32 * 60;
#pragma unroll
    for (int mt = 0; mt < 2; mt++) {
#pragma unroll
        for (int rh = 0; rh < 2; rh++) {
            int irow = warp * 32 + mt * 16 + g + rh * 8;
            bool vi = (irow < 49);
            const float* bmr = bmp + irow * 49;
            float vals[14];
#pragma unroll
            for (int tj = 0; tj < 7; tj++) {
#pragma unroll
                for (int cc = 0; cc < 2; cc++) {
                    int j = tj * 8 + 2 * t + cc;
                    float s = acc[mt][tj][rh * 2 + cc];
                    s = (vi && j < 49) ? (s + bmr[j]) : -1e30f;
                    vals[tj * 2 + cc] = s;
                }
            }
            float m = vals[0];
#pragma unroll
            for (int u = 1; u < 14; u++) m = fmaxf(m, vals[u]);
            m = fmaxf(m, __shfl_xor_sync(0xffffffffu, m, 1));
            m = fmaxf(m, __shfl_xor_sync(0xffffffffu, m, 2));
            float ssum = 0.f;
#pragma unroll
            for (int u = 0; u < 14; u++) { vals[u] = __expf(vals[u] - m); ssum += vals[u]; }
            ssum += __shfl_xor_sync(0xffffffffu, ssum, 1);
            ssum += __shfl_xor_sync(0xffffffffu, ssum, 2);
            float inv = __frcp_rn(ssum);
            float* prow = sP_w + (mt * 16 + g + rh * 8) * 60;
#pragma unroll
            for (int tj = 0; tj < 7; tj++) {
                float2 p2 = make_float2(to_tf32(vals[tj * 2] * inv),
                                        to_tf32(vals[tj * 2 + 1] * inv));
                *(float2*)(prow + tj * 8 + 2 * t) = p2;
            }
        }
    }
    __syncwarp();

    float pacc[2][4][4] = {};
#pragma unroll
    for (int kc = 0; kc < 7; kc++) {
        uint32_t a[2][4];
#pragma unroll
        for (int mt = 0; mt < 2; mt++) {
            const float* pr = sP_w + (mt * 16 + g) * 60 + kc * 8;
            a[mt][0] = __float_as_uint(pr[t]);
            a[mt][1] = __float_as_uint(pr[8 * 60 + t]);
            a[mt][2] = __float_as_uint(pr[t + 4]);
            a[mt][3] = __float_as_uint(pr[8 * 60 + t + 4]);
        }
        int j0 = kc * 8 + t;
        int j1 = kc * 8 + t + 4;
#pragma unroll
        for (int nt = 0; nt < 4; nt++) {
            int d = nt * 8 + g;
            uint32_t bb[2];
            bb[0] = (j0 < 49) ? __float_as_uint(to_tf32(vb[j0 * 32 + d])) : 0u;
            bb[1] = (j1 < 49) ? __float_as_uint(to_tf32(vb[j1 * 32 + d])) : 0u;
            mma_tf32(pacc[0][nt], a[0], bb);
            mma_tf32(pacc[1][nt], a[1], bb);
        }
    }

    // store rows i < 49, tf32-rounded so proj consumes pre-converted input
#pragma unroll
    for (int mt = 0; mt < 2; mt++) {
#pragma unroll
        for (int rh = 0; rh < 2; rh++) {
            int irow = warp * 32 + mt * 16 + g + rh * 8;
            if (irow < 49) {
                float* op = g_attn + ((size_t)b * 49 + irow) * 256 + h * 32;
#pragma unroll
                for (int nt = 0; nt < 4; nt++) {
                    int d = nt * 8 + 2 * t;
                    *(float2*)(op + d) =
                        make_float2(to_tf32(pacc[mt][nt][rh * 2 + 0]),
                                    to_tf32(pacc[mt][nt][rh * 2 + 1]));
                }
            }
        }
    }
}

// ---------------------------------------------------------------------------
extern "C" void kernel_launch(void* const* d_in, const int* in_sizes, int n_in,
                              void* d_out, int out_size)
{
    const float* x      = (const float*)d_in[0];
    const float* mask   = (const float*)d_in[1];
    const float* qkv_w  = (const float*)d_in[2];
    const float* qkv_b  = (const float*)d_in[3];
    const float* proj_w = (const float*)d_in[4];
    const float* proj_b = (const float*)d_in[5];
    const float* bt     = (const float*)d_in[6];
    float* out = (float*)d_out;

    cudaFuncSetAttribute((const void*)gemm128_ca<true>,
                         cudaFuncAttributeMaxDynamicSharedMemorySize, GEMM_CA_SMEM);
    cudaFuncSetAttribute((const void*)gemm128_ca<false>,
                         cudaFuncAttributeMaxDynamicSharedMemorySize, GEMM_CA_SMEM);

    cvt_tf32_kernel<<<2048, 256>>>(x, M_ROWS * C_DIM / 4, 0);
    cvt_tf32_kernel<<<192, 256>>>(qkv_w, 768 * 256 / 4, 1);
    cvt_tf32_kernel<<<64, 256>>>(proj_w, 256 * 256 / 4, 2);
    fuse_bm_kernel<<<512, 256>>>(mask, bt);

    gemm128_ca<true><<<dim3(M_ROWS / 128, 6), 256, GEMM_CA_SMEM>>>(qkv_b, nullptr);
    attn_slim_kernel<<<B_WIN * H_NUM, 64>>>();
    gemm128_ca<false><<<dim3(M_ROWS / 128, 2), 256, GEMM_CA_SMEM>>>(proj_b, out);
}

// round 9
// speedup vs baseline: 1.6842x; 1.0171x over previous
#include <cuda_runtime.h>
#include <cstdint>

#define N_TOK   49
#define C_DIM   256
#define H_NUM   8
#define HD      32
#define B_WIN   4096
#define M_ROWS  (B_WIN * N_TOK)   // 200704

// Scratch (allocation-free rule: __device__ globals)
__device__ float g_qkv[(size_t)B_WIN * H_NUM * 3 * N_TOK * HD];   // 616 MB
__device__ float g_attn[(size_t)M_ROWS * C_DIM];                  // 205 MB (tf32-rounded)
__device__ float g_xcvt[(size_t)M_ROWS * C_DIM];                  // 205 MB (tf32-rounded x)
__device__ float g_wq[768 * 256];                                 // tf32-rounded qkv_w
__device__ float g_wp[256 * 256];                                 // tf32-rounded proj_w
__device__ float g_bm[512 * 2401];                                // bias+mask, 4.9 MB

// ---------------------------------------------------------------------------
__device__ __forceinline__ float to_tf32(float x) {
    uint32_t u;
    asm("cvt.rna.tf32.f32 %0, %1;" : "=r"(u) : "f"(x));
    return __uint_as_float(u);
}

__device__ __forceinline__ void mma_tf32(float c[4], const uint32_t a[4], const uint32_t b[2]) {
    asm volatile(
        "mma.sync.aligned.m16n8k8.row.col.f32.tf32.tf32.f32 "
        "{%0,%1,%2,%3}, {%4,%5,%6,%7}, {%8,%9}, {%0,%1,%2,%3};"
        : "+f"(c[0]), "+f"(c[1]), "+f"(c[2]), "+f"(c[3])
        : "r"(a[0]), "r"(a[1]), "r"(a[2]), "r"(a[3]), "r"(b[0]), "r"(b[1]));
}

__device__ __forceinline__ void cp16(uint32_t smem_addr, const float* gptr) {
    asm volatile("cp.async.cg.shared.global [%0], [%1], 16;"
                 :: "r"(smem_addr), "l"(gptr) : "memory");
}
__device__ __forceinline__ void cp_commit() {
    asm volatile("cp.async.commit_group;" ::: "memory");
}
template<int N>
__device__ __forceinline__ void cp_wait() {
    asm volatile("cp.async.wait_group %0;" :: "n"(N) : "memory");
}

// ---------------------------------------------------------------------------
// Kernel A: tf32 pre-convert (grid-stride over float4)
//   which: 0 -> g_xcvt, 1 -> g_wq, 2 -> g_wp
// ---------------------------------------------------------------------------
__global__ __launch_bounds__(256) void cvt_tf32_kernel(
    const float* __restrict__ src, int n4, int which)
{
    float* dst = (which == 0) ? g_xcvt : (which == 1) ? g_wq : g_wp;
    int idx = blockIdx.x * blockDim.x + threadIdx.x;
    int stride = gridDim.x * blockDim.x;
    for (; idx < n4; idx += stride) {
        float4 v = ((const float4*)src)[idx];
        v.x = to_tf32(v.x); v.y = to_tf32(v.y);
        v.z = to_tf32(v.z); v.w = to_tf32(v.w);
        ((float4*)dst)[idx] = v;
    }
}

// ---------------------------------------------------------------------------
// GEMM: CTA tile 128x128, warp tile 64x32, cp.async double-buffered slabs.
// Inputs are pre-converted to tf32 (g_xcvt/g_wq or g_attn/g_wp).
// dynamic smem: 2 * (128*36 A + 128*36 B) * 4 = 73728 B
// ---------------------------------------------------------------------------
#define SLAB_FLOATS (128 * 36)
#define GEMM_CA_SMEM (4 * SLAB_FLOATS * 4)

template<bool QKV_MODE>
__global__ __launch_bounds__(256) void gemm128_ca(
    const float* __restrict__ bias, float* __restrict__ out)
{
    extern __shared__ float sm[];
    // layout: As[0], As[1], Bs[0], Bs[1] each SLAB_FLOATS
    const uint32_t sm_u32 = (uint32_t)__cvta_generic_to_shared(sm);

    const int tid = threadIdx.x;
    const int mBase = blockIdx.x * 128;
    const int nBase = blockIdx.y * 128;
    const float* X = QKV_MODE ? g_xcvt : g_attn;
    const float* W = QKV_MODE ? g_wq : g_wp;

    const int warp = tid >> 5, lane = tid & 31;
    const int wm = (warp & 1) * 64, wn = (warp >> 1) * 32;
    const int g = lane >> 2, t = lane & 3;

    // staging coords (per thread): rows r0+{0,32,64,96}, cols c0..c0+3
    const int r0 = tid >> 3;
    const int c0 = (tid & 7) * 4;

    // issue slab ks into buffer buf
    auto issue = [&](int ks, int buf) {
        const float* xrow = X + (size_t)(mBase + r0) * 256 + ks * 32 + c0;
        const float* wrow = W + (size_t)(nBase + r0) * 256 + ks * 32 + c0;
        uint32_t adstA = sm_u32 + (uint32_t)((buf * SLAB_FLOATS + r0 * 36 + c0) * 4);
        uint32_t adstB = sm_u32 + (uint32_t)((2 * SLAB_FLOATS + buf * SLAB_FLOATS + r0 * 36 + c0) * 4);
#pragma unroll
        for (int p = 0; p < 4; p++) {
            cp16(adstA + p * 32 * 36 * 4, xrow + (size_t)p * 32 * 256);
            cp16(adstB + p * 32 * 36 * 4, wrow + (size_t)p * 32 * 256);
        }
        cp_commit();
    };

    float acc[4][4][4] = {};

    issue(0, 0);
    for (int ks = 0; ks < 8; ks++) {
        const int buf = ks & 1;
        if (ks < 7) issue(ks + 1, buf ^ 1);
        if (ks < 7) cp_wait<1>(); else cp_wait<0>();
        __syncthreads();

        const float* As = sm + buf * SLAB_FLOATS;
        const float* Bs = sm + 2 * SLAB_FLOATS + buf * SLAB_FLOATS;

#pragma unroll
        for (int ko = 0; ko < 32; ko += 8) {
            uint32_t a[4][4], bb[4][2];
#pragma unroll
            for (int mi = 0; mi < 4; mi++) {
                int row = wm + mi * 16 + g;
                a[mi][0] = __float_as_uint(As[row * 36 + ko + t]);
                a[mi][1] = __float_as_uint(As[(row + 8) * 36 + ko + t]);
                a[mi][2] = __float_as_uint(As[row * 36 + ko + t + 4]);
                a[mi][3] = __float_as_uint(As[(row + 8) * 36 + ko + t + 4]);
            }
#pragma unroll
            for (int ni = 0; ni < 4; ni++) {
                int col = wn + ni * 8 + g;
                bb[ni][0] = __float_as_uint(Bs[col * 36 + ko + t]);
                bb[ni][1] = __float_as_uint(Bs[col * 36 + ko + t + 4]);
            }
#pragma unroll
            for (int mi = 0; mi < 4; mi++)
#pragma unroll
                for (int ni = 0; ni < 4; ni++)
                    mma_tf32(acc[mi][ni], a[mi], bb[ni]);
        }
        __syncthreads();   // all warps done reading buf before it is re-issued
    }

    const float qscale = 0.17677669529663687f;
#pragma unroll
    for (int mi = 0; mi < 4; mi++) {
#pragma unroll
        for (int ni = 0; ni < 4; ni++) {
            int gn = nBase + wn + ni * 8 + t * 2;
            float bv0 = bias[gn], bv1 = bias[gn + 1];
            if (QKV_MODE) {
                int which = gn >> 8;
                int h = (gn >> 5) & 7;
                int d = gn & 31;
                float sc = (which == 0) ? qscale : 1.0f;
#pragma unroll
                for (int half = 0; half < 2; half++) {
                    int gm = mBase + wm + mi * 16 + g + half * 8;
                    int b = gm / 49;
                    int r = gm - b * 49;
                    float v0 = (acc[mi][ni][half * 2 + 0] + bv0) * sc;
                    float v1 = (acc[mi][ni][half * 2 + 1] + bv1) * sc;
                    size_t off = ((((size_t)b * 8 + h) * 3 + which) * 49 + r) * 32 + d;
                    *(float2*)(g_qkv + off) = make_float2(v0, v1);
                }
            } else {
#pragma unroll
                for (int half = 0; half < 2; half++) {
                    int gm = mBase + wm + mi * 16 + g + half * 8;
                    float v0 = acc[mi][ni][half * 2 + 0] + bv0;
                    float v1 = acc[mi][ni][half * 2 + 1] + bv1;
                    *(float2*)(out + (size_t)gm * 256 + gn) = make_float2(v0, v1);
                }
            }
        }
    }
}

// ---------------------------------------------------------------------------
// Kernel 0: fuse bias_table + mask -> g_bm[(w*8+h)][i*49+j]
// ---------------------------------------------------------------------------
__global__ __launch_bounds__(256) void fuse_bm_kernel(
    const float* __restrict__ mask, const float* __restrict__ bt)
{
    const int wh = blockIdx.x;          // 0..511
    const int w = wh >> 3, h = wh & 7;
    const float* mw = mask + (size_t)w * 2401;
    float* dst = g_bm + (size_t)wh * 2401;
    for (int idx = threadIdx.x; idx < 2401; idx += 256) {
        int i = idx / 49, j = idx - i * 49;
        int ri = i / 7, ci = i - ri * 7;
        int rj = j / 7, cj = j - rj * 7;
        int bidx = (ri - rj + 6) * 13 + (ci - cj + 6);
        dst[idx] = mw[idx] + bt[bidx * 8 + h];
    }
}

// ---------------------------------------------------------------------------
// Slim tensor-core attention (R6, proven ~350us): one CTA per (window, head),
// 64 threads. Output stored tf32-rounded so proj can consume it directly.
// ---------------------------------------------------------------------------
__global__ __launch_bounds__(64) void attn_slim_kernel()
{
    __shared__ float sP[2 * 32 * 60];

    const int bh   = blockIdx.x;
    const int b    = bh >> 3;
    const int h    = bh & 7;
    const int warp = threadIdx.x >> 5;
    const int lane = threadIdx.x & 31;
    const int g = lane >> 2, t = lane & 3;

    const float* qb = g_qkv + (size_t)bh * 3 * 1568;
    const float* kb = qb + 1568;
    const float* vb = qb + 2 * 1568;

    float acc[2][7][4] = {};
#pragma unroll
    for (int kc = 0; kc < 4; kc++) {
        uint32_t a[2][4];
#pragma unroll
        for (int mt = 0; mt < 2; mt++) {
            const float* qr = qb + (warp * 32 + mt * 16 + g) * 32 + kc * 8;
            a[mt][0] = __float_as_uint(to_tf32(qr[t]));
            a[mt][1] = __float_as_uint(to_tf32(qr[8 * 32 + t]));
            a[mt][2] = __float_as_uint(to_tf32(qr[t + 4]));
            a[mt][3] = __float_as_uint(to_tf32(qr[8 * 32 + t + 4]));
        }
#pragma unroll
        for (int tj = 0; tj < 7; tj++) {
            const float* kr = kb + (tj * 8 + g) * 32 + kc * 8;
            uint32_t bb[2];
            bb[0] = __float_as_uint(to_tf32(kr[t]));
            bb[1] = __float_as_uint(to_tf32(kr[t + 4]));
            mma_tf32(acc[0][tj], a[0], bb);
            mma_tf32(acc[1][tj], a[1], bb);
        }
    }

    const float* bmp = g_bm + ((size_t)((b & 63) * 8 + h)) * 2401;
    float* sP_w = sP + warp * 32 * 60;
#pragma unroll
    for (int mt = 0; mt < 2; mt++) {
#pragma unroll
        for (int rh = 0; rh < 2; rh++) {
            int irow = warp * 32 + mt * 16 + g + rh * 8;
            bool vi = (irow < 49);
            const float* bmr = bmp + irow * 49;
            float vals[14];
#pragma unroll
            for (int tj = 0; tj < 7; tj++) {
#pragma unroll
                for (int cc = 0; cc < 2; cc++) {
                    int j = tj * 8 + 2 * t + cc;
                    float s = acc[mt][tj][rh * 2 + cc];
                    s = (vi && j < 49) ? (s + bmr[j]) : -1e30f;
                    vals[tj * 2 + cc] = s;
                }
            }
            float m = vals[0];
#pragma unroll
            for (int u = 1; u < 14; u++) m = fmaxf(m, vals[u]);
            m = fmaxf(m, __shfl_xor_sync(0xffffffffu, m, 1));
            m = fmaxf(m, __shfl_xor_sync(0xffffffffu, m, 2));
            float ssum = 0.f;
#pragma unroll
            for (int u = 0; u < 14; u++) { vals[u] = __expf(vals[u] - m); ssum += vals[u]; }
            ssum += __shfl_xor_sync(0xffffffffu, ssum, 1);
            ssum += __shfl_xor_sync(0xffffffffu, ssum, 2);
            float inv = __frcp_rn(ssum);
            float* prow = sP_w + (mt * 16 + g + rh * 8) * 60;
#pragma unroll
            for (int tj = 0; tj < 7; tj++) {
                float2 p2 = make_float2(to_tf32(vals[tj * 2] * inv),
                                        to_tf32(vals[tj * 2 + 1] * inv));
                *(float2*)(prow + tj * 8 + 2 * t) = p2;
            }
        }
    }
    __syncwarp();

    float pacc[2][4][4] = {};
#pragma unroll
    for (int kc = 0; kc < 7; kc++) {
        uint32_t a[2][4];
#pragma unroll
        for (int mt = 0; mt < 2; mt++) {
            const float* pr = sP_w + (mt * 16 + g) * 60 + kc * 8;
            a[mt][0] = __float_as_uint(pr[t]);
            a[mt][1] = __float_as_uint(pr[8 * 60 + t]);
            a[mt][2] = __float_as_uint(pr[t + 4]);
            a[mt][3] = __float_as_uint(pr[8 * 60 + t + 4]);
        }
        int j0 = kc * 8 + t;
        int j1 = kc * 8 + t + 4;
#pragma unroll
        for (int nt = 0; nt < 4; nt++) {
            int d = nt * 8 + g;
            uint32_t bb[2];
            bb[0] = (j0 < 49) ? __float_as_uint(to_tf32(vb[j0 * 32 + d])) : 0u;
            bb[1] = (j1 < 49) ? __float_as_uint(to_tf32(vb[j1 * 32 + d])) : 0u;
            mma_tf32(pacc[0][nt], a[0], bb);
            mma_tf32(pacc[1][nt], a[1], bb);
        }
    }

    // store rows i < 49, tf32-rounded so proj consumes pre-converted input
#pragma unroll
    for (int mt = 0; mt < 2; mt++) {
#pragma unroll
        for (int rh = 0; rh < 2; rh++) {
            int irow = warp * 32 + mt * 16 + g + rh * 8;
            if (irow < 49) {
                float* op = g_attn + ((size_t)b * 49 + irow) * 256 + h * 32;
#pragma unroll
                for (int nt = 0; nt < 4; nt++) {
                    int d = nt * 8 + 2 * t;
                    *(float2*)(op + d) =
                        make_float2(to_tf32(pacc[mt][nt][rh * 2 + 0]),
                                    to_tf32(pacc[mt][nt][rh * 2 + 1]));
                }
            }
        }
    }
}

// ---------------------------------------------------------------------------
extern "C" void kernel_launch(void* const* d_in, const int* in_sizes, int n_in,
                              void* d_out, int out_size)
{
    const float* x      = (const float*)d_in[0];
    const float* mask   = (const float*)d_in[1];
    const float* qkv_w  = (const float*)d_in[2];
    const float* qkv_b  = (const float*)d_in[3];
    const float* proj_w = (const float*)d_in[4];
    const float* proj_b = (const float*)d_in[5];
    const float* bt     = (const float*)d_in[6];
    float* out = (float*)d_out;

    cudaFuncSetAttribute((const void*)gemm128_ca<true>,
                         cudaFuncAttributeMaxDynamicSharedMemorySize, GEMM_CA_SMEM);
    cudaFuncSetAttribute((const void*)gemm128_ca<false>,
                         cudaFuncAttributeMaxDynamicSharedMemorySize, GEMM_CA_SMEM);

    cvt_tf32_kernel<<<2048, 256>>>(x, M_ROWS * C_DIM / 4, 0);
    cvt_tf32_kernel<<<192, 256>>>(qkv_w, 768 * 256 / 4, 1);
    cvt_tf32_kernel<<<64, 256>>>(proj_w, 256 * 256 / 4, 2);
    fuse_bm_kernel<<<512, 256>>>(mask, bt);

    gemm128_ca<true><<<dim3(M_ROWS / 128, 6), 256, GEMM_CA_SMEM>>>(qkv_b, nullptr);
    attn_slim_kernel<<<B_WIN * H_NUM, 64>>>();
    gemm128_ca<false><<<dim3(M_ROWS / 128, 2), 256, GEMM_CA_SMEM>>>(proj_b, out);
}

// round 11
// speedup vs baseline: 1.6985x; 1.0085x over previous
#include <cuda_runtime.h>
#include <cstdint>

#define N_TOK   49
#define C_DIM   256
#define H_NUM   8
#define HD      32
#define B_WIN   4096
#define M_ROWS  (B_WIN * N_TOK)   // 200704

// Scratch (allocation-free rule: __device__ globals)
__device__ float g_qkv[(size_t)B_WIN * H_NUM * 3 * N_TOK * HD];   // 616 MB
__device__ float g_attn[(size_t)M_ROWS * C_DIM];                  // 205 MB (tf32-rounded)
__device__ float g_xcvt[(size_t)M_ROWS * C_DIM];                  // 205 MB (tf32-rounded x)
__device__ float g_wq[768 * 256];                                 // tf32-rounded qkv_w
__device__ float g_wp[256 * 256];                                 // tf32-rounded proj_w
__device__ float g_bm[512 * 2401];                                // bias+mask, 4.9 MB

// ---------------------------------------------------------------------------
__device__ __forceinline__ float to_tf32(float x) {
    uint32_t u;
    asm("cvt.rna.tf32.f32 %0, %1;" : "=r"(u) : "f"(x));
    return __uint_as_float(u);
}

__device__ __forceinline__ void mma_tf32(float c[4], const uint32_t a[4], const uint32_t b[2]) {
    asm volatile(
        "mma.sync.aligned.m16n8k8.row.col.f32.tf32.tf32.f32 "
        "{%0,%1,%2,%3}, {%4,%5,%6,%7}, {%8,%9}, {%0,%1,%2,%3};"
        : "+f"(c[0]), "+f"(c[1]), "+f"(c[2]), "+f"(c[3])
        : "r"(a[0]), "r"(a[1]), "r"(a[2]), "r"(a[3]), "r"(b[0]), "r"(b[1]));
}

__device__ __forceinline__ void cp16(uint32_t smem_addr, const float* gptr) {
    asm volatile("cp.async.cg.shared.global [%0], [%1], 16;"
                 :: "r"(smem_addr), "l"(gptr) : "memory");
}
__device__ __forceinline__ void cp_commit() {
    asm volatile("cp.async.commit_group;" ::: "memory");
}
template<int N>
__device__ __forceinline__ void cp_wait() {
    asm volatile("cp.async.wait_group %0;" :: "n"(N) : "memory");
}

// ---------------------------------------------------------------------------
// Kernel A: tf32 pre-convert (grid-stride over float4)
//   which: 0 -> g_xcvt, 1 -> g_wq, 2 -> g_wp
// ---------------------------------------------------------------------------
__global__ __launch_bounds__(256) void cvt_tf32_kernel(
    const float* __restrict__ src, int n4, int which)
{
    float* dst = (which == 0) ? g_xcvt : (which == 1) ? g_wq : g_wp;
    int idx = blockIdx.x * blockDim.x + threadIdx.x;
    int stride = gridDim.x * blockDim.x;
    for (; idx < n4; idx += stride) {
        float4 v = ((const float4*)src)[idx];
        v.x = to_tf32(v.x); v.y = to_tf32(v.y);
        v.z = to_tf32(v.z); v.w = to_tf32(v.w);
        ((float4*)dst)[idx] = v;
    }
}

// ---------------------------------------------------------------------------
// GEMM: CTA tile 128x128, warp tile 64x32, cp.async double-buffered slabs.
// Grid: x = N-chunk (small), y = M-tile (1568). x-major CTA order makes
// consecutive CTAs cover all N-chunks of the same M-tiles -> X stays in L2
// (only 1 DRAM read of X instead of gridDim.x).
// dynamic smem: 2 * (128*36 A + 128*36 B) * 4 = 73728 B
// ---------------------------------------------------------------------------
#define SLAB_FLOATS (128 * 36)
#define GEMM_CA_SMEM (4 * SLAB_FLOATS * 4)

template<bool QKV_MODE>
__global__ __launch_bounds__(256) void gemm128_ca(
    const float* __restrict__ bias, float* __restrict__ out)
{
    extern __shared__ float sm[];
    // layout: As[0], As[1], Bs[0], Bs[1] each SLAB_FLOATS
    const uint32_t sm_u32 = (uint32_t)__cvta_generic_to_shared(sm);

    const int tid = threadIdx.x;
    const int mBase = blockIdx.y * 128;   // M on y (large)
    const int nBase = blockIdx.x * 128;   // N on x (small) -> L2 reuse of X
    const float* X = QKV_MODE ? g_xcvt : g_attn;
    const float* W = QKV_MODE ? g_wq : g_wp;

    const int warp = tid >> 5, lane = tid & 31;
    const int wm = (warp & 1) * 64, wn = (warp >> 1) * 32;
    const int g = lane >> 2, t = lane & 3;

    // staging coords (per thread): rows r0+{0,32,64,96}, cols c0..c0+3
    const int r0 = tid >> 3;
    const int c0 = (tid & 7) * 4;

    // issue slab ks into buffer buf
    auto issue = [&](int ks, int buf) {
        const float* xrow = X + (size_t)(mBase + r0) * 256 + ks * 32 + c0;
        const float* wrow = W + (size_t)(nBase + r0) * 256 + ks * 32 + c0;
        uint32_t adstA = sm_u32 + (uint32_t)((buf * SLAB_FLOATS + r0 * 36 + c0) * 4);
        uint32_t adstB = sm_u32 + (uint32_t)((2 * SLAB_FLOATS + buf * SLAB_FLOATS + r0 * 36 + c0) * 4);
#pragma unroll
        for (int p = 0; p < 4; p++) {
            cp16(adstA + p * 32 * 36 * 4, xrow + (size_t)p * 32 * 256);
            cp16(adstB + p * 32 * 36 * 4, wrow + (size_t)p * 32 * 256);
        }
        cp_commit();
    };

    float acc[4][4][4] = {};

    issue(0, 0);
    for (int ks = 0; ks < 8; ks++) {
        const int buf = ks & 1;
        if (ks < 7) issue(ks + 1, buf ^ 1);
        if (ks < 7) cp_wait<1>(); else cp_wait<0>();
        __syncthreads();

        const float* As = sm + buf * SLAB_FLOATS;
        const float* Bs = sm + 2 * SLAB_FLOATS + buf * SLAB_FLOATS;

#pragma unroll
        for (int ko = 0; ko < 32; ko += 8) {
            uint32_t a[4][4], bb[4][2];
#pragma unroll
            for (int mi = 0; mi < 4; mi++) {
                int row = wm + mi * 16 + g;
                a[mi][0] = __float_as_uint(As[row * 36 + ko + t]);
                a[mi][1] = __float_as_uint(As[(row + 8) * 36 + ko + t]);
                a[mi][2] = __float_as_uint(As[row * 36 + ko + t + 4]);
                a[mi][3] = __float_as_uint(As[(row + 8) * 36 + ko + t + 4]);
            }
#pragma unroll
            for (int ni = 0; ni < 4; ni++) {
                int col = wn + ni * 8 + g;
                bb[ni][0] = __float_as_uint(Bs[col * 36 + ko + t]);
                bb[ni][1] = __float_as_uint(Bs[col * 36 + ko + t + 4]);
            }
#pragma unroll
            for (int mi = 0; mi < 4; mi++)
#pragma unroll
                for (int ni = 0; ni < 4; ni++)
                    mma_tf32(acc[mi][ni], a[mi], bb[ni]);
        }
        __syncthreads();   // all warps done reading buf before it is re-issued
    }

    const float qscale = 0.17677669529663687f;
#pragma unroll
    for (int mi = 0; mi < 4; mi++) {
#pragma unroll
        for (int ni = 0; ni < 4; ni++) {
            int gn = nBase + wn + ni * 8 + t * 2;
            float bv0 = bias[gn], bv1 = bias[gn + 1];
            if (QKV_MODE) {
                int which = gn >> 8;
                int h = (gn >> 5) & 7;
                int d = gn & 31;
                float sc = (which == 0) ? qscale : 1.0f;
#pragma unroll
                for (int half = 0; half < 2; half++) {
                    int gm = mBase + wm + mi * 16 + g + half * 8;
                    int b = gm / 49;
                    int r = gm - b * 49;
                    float v0 = (acc[mi][ni][half * 2 + 0] + bv0) * sc;
                    float v1 = (acc[mi][ni][half * 2 + 1] + bv1) * sc;
                    size_t off = ((((size_t)b * 8 + h) * 3 + which) * 49 + r) * 32 + d;
                    *(float2*)(g_qkv + off) = make_float2(v0, v1);
                }
            } else {
#pragma unroll
                for (int half = 0; half < 2; half++) {
                    int gm = mBase + wm + mi * 16 + g + half * 8;
                    float v0 = acc[mi][ni][half * 2 + 0] + bv0;
                    float v1 = acc[mi][ni][half * 2 + 1] + bv1;
                    *(float2*)(out + (size_t)gm * 256 + gn) = make_float2(v0, v1);
                }
            }
        }
    }
}

// ---------------------------------------------------------------------------
// Kernel 0: fuse bias_table + mask -> g_bm[(w*8+h)][i*49+j]
// ---------------------------------------------------------------------------
__global__ __launch_bounds__(256) void fuse_bm_kernel(
    const float* __restrict__ mask, const float* __restrict__ bt)
{
    const int wh = blockIdx.x;          // 0..511
    const int w = wh >> 3, h = wh & 7;
    const float* mw = mask + (size_t)w * 2401;
    float* dst = g_bm + (size_t)wh * 2401;
    for (int idx = threadIdx.x; idx < 2401; idx += 256) {
        int i = idx / 49, j = idx - i * 49;
        int ri = i / 7, ci = i - ri * 7;
        int rj = j / 7, cj = j - rj * 7;
        int bidx = (ri - rj + 6) * 13 + (ci - cj + 6);
        dst[idx] = mw[idx] + bt[bidx * 8 + h];
    }
}

// ---------------------------------------------------------------------------
// Slim tensor-core attention (R6, proven): one CTA per (window, head),
// 64 threads. Output stored tf32-rounded so proj can consume it directly.
// ---------------------------------------------------------------------------
__global__ __launch_bounds__(64) void attn_slim_kernel()
{
    __shared__ float sP[2 * 32 * 60];

    const int bh   = blockIdx.x;
    const int b    = bh >> 3;
    const int h    = bh & 7;
    const int warp = threadIdx.x >> 5;
    const int lane = threadIdx.x & 31;
    const int g = lane >> 2, t = lane & 3;

    const float* qb = g_qkv + (size_t)bh * 3 * 1568;
    const float* kb = qb + 1568;
    const float* vb = qb + 2 * 1568;

    float acc[2][7][4] = {};
#pragma unroll
    for (int kc = 0; kc < 4; kc++) {
        uint32_t a[2][4];
#pragma unroll
        for (int mt = 0; mt < 2; mt++) {
            const float* qr = qb + (warp * 32 + mt * 16 + g) * 32 + kc * 8;
            a[mt][0] = __float_as_uint(to_tf32(qr[t]));
            a[mt][1] = __float_as_uint(to_tf32(qr[8 * 32 + t]));
            a[mt][2] = __float_as_uint(to_tf32(qr[t + 4]));
            a[mt][3] = __float_as_uint(to_tf32(qr[8 * 32 + t + 4]));
        }
#pragma unroll
        for (int tj = 0; tj < 7; tj++) {
            const float* kr = kb + (tj * 8 + g) * 32 + kc * 8;
            uint32_t bb[2];
            bb[0] = __float_as_uint(to_tf32(kr[t]));
            bb[1] = __float_as_uint(to_tf32(kr[t + 4]));
            mma_tf32(acc[0][tj], a[0], bb);
            mma_tf32(acc[1][tj], a[1], bb);
        }
    }

    const float* bmp = g_bm + ((size_t)((b & 63) * 8 + h)) * 2401;
    float* sP_w = sP + warp * 32 * 60;
#pragma unroll
    for (int mt = 0; mt < 2; mt++) {
#pragma unroll
        for (int rh = 0; rh < 2; rh++) {
            int irow = warp * 32 + mt * 16 + g + rh * 8;
            bool vi = (irow < 49);
            const float* bmr = bmp + irow * 49;
            float vals[14];
#pragma unroll
            for (int tj = 0; tj < 7; tj++) {
#pragma unroll
                for (int cc = 0; cc < 2; cc++) {
                    int j = tj * 8 + 2 * t + cc;
                    float s = acc[mt][tj][rh * 2 + cc];
                    s = (vi && j < 49) ? (s + bmr[j]) : -1e30f;
                    vals[tj * 2 + cc] = s;
                }
            }
            float m = vals[0];
#pragma unroll
            for (int u = 1; u < 14; u++) m = fmaxf(m, vals[u]);
            m = fmaxf(m, __shfl_xor_sync(0xffffffffu, m, 1));
            m = fmaxf(m, __shfl_xor_sync(0xffffffffu, m, 2));
            float ssum = 0.f;
#pragma unroll
            for (int u = 0; u < 14; u++) { vals[u] = __expf(vals[u] - m); ssum += vals[u]; }
            ssum += __shfl_xor_sync(0xffffffffu, ssum, 1);
            ssum += __shfl_xor_sync(0xffffffffu, ssum, 2);
            float inv = __frcp_rn(ssum);
            float* prow = sP_w + (mt * 16 + g + rh * 8) * 60;
#pragma unroll
            for (int tj = 0; tj < 7; tj++) {
                float2 p2 = make_float2(to_tf32(vals[tj * 2] * inv),
                                        to_tf32(vals[tj * 2 + 1] * inv));
                *(float2*)(prow + tj * 8 + 2 * t) = p2;
            }
        }
    }
    __syncwarp();

    float pacc[2][4][4] = {};
#pragma unroll
    for (int kc = 0; kc < 7; kc++) {
        uint32_t a[2][4];
#pragma unroll
        for (int mt = 0; mt < 2; mt++) {
            const float* pr = sP_w + (mt * 16 + g) * 60 + kc * 8;
            a[mt][0] = __float_as_uint(pr[t]);
            a[mt][1] = __float_as_uint(pr[8 * 60 + t]);
            a[mt][2] = __float_as_uint(pr[t + 4]);
            a[mt][3] = __float_as_uint(pr[8 * 60 + t + 4]);
        }
        int j0 = kc * 8 + t;
        int j1 = kc * 8 + t + 4;
#pragma unroll
        for (int nt = 0; nt < 4; nt++) {
            int d = nt * 8 + g;
            uint32_t bb[2];
            bb[0] = (j0 < 49) ? __float_as_uint(to_tf32(vb[j0 * 32 + d])) : 0u;
            bb[1] = (j1 < 49) ? __float_as_uint(to_tf32(vb[j1 * 32 + d])) : 0u;
            mma_tf32(pacc[0][nt], a[0], bb);
            mma_tf32(pacc[1][nt], a[1], bb);
        }
    }

    // store rows i < 49, tf32-rounded so proj consumes pre-converted input
#pragma unroll
    for (int mt = 0; mt < 2; mt++) {
#pragma unroll
        for (int rh = 0; rh < 2; rh++) {
            int irow = warp * 32 + mt * 16 + g + rh * 8;
            if (irow < 49) {
                float* op = g_attn + ((size_t)b * 49 + irow) * 256 + h * 32;
#pragma unroll
                for (int nt = 0; nt < 4; nt++) {
                    int d = nt * 8 + 2 * t;
                    *(float2*)(op + d) =
                        make_float2(to_tf32(pacc[mt][nt][rh * 2 + 0]),
                                    to_tf32(pacc[mt][nt][rh * 2 + 1]));
                }
            }
        }
    }
}

// ---------------------------------------------------------------------------
extern "C" void kernel_launch(void* const* d_in, const int* in_sizes, int n_in,
                              void* d_out, int out_size)
{
    const float* x      = (const float*)d_in[0];
    const float* mask   = (const float*)d_in[1];
    const float* qkv_w  = (const float*)d_in[2];
    const float* qkv_b  = (const float*)d_in[3];
    const float* proj_w = (const float*)d_in[4];
    const float* proj_b = (const float*)d_in[5];
    const float* bt     = (const float*)d_in[6];
    float* out = (float*)d_out;

    cudaFuncSetAttribute((const void*)gemm128_ca<true>,
                         cudaFuncAttributeMaxDynamicSharedMemorySize, GEMM_CA_SMEM);
    cudaFuncSetAttribute((const void*)gemm128_ca<false>,
                         cudaFuncAttributeMaxDynamicSharedMemorySize, GEMM_CA_SMEM);

    cvt_tf32_kernel<<<2048, 256>>>(x, M_ROWS * C_DIM / 4, 0);
    cvt_tf32_kernel<<<192, 256>>>(qkv_w, 768 * 256 / 4, 1);
    cvt_tf32_kernel<<<64, 256>>>(proj_w, 256 * 256 / 4, 2);
    fuse_bm_kernel<<<512, 256>>>(mask, bt);

    // grid: x = N-chunks (small), y = M-tiles (1568) -> X reuse via L2
    gemm128_ca<true><<<dim3(6, M_ROWS / 128), 256, GEMM_CA_SMEM>>>(qkv_b, nullptr);
    attn_slim_kernel<<<B_WIN * H_NUM, 64>>>();
    gemm128_ca<false><<<dim3(2, M_ROWS / 128), 256, GEMM_CA_SMEM>>>(proj_b, out);
}

// round 13
// speedup vs baseline: 1.7780x; 1.0468x over previous
#include <cuda_runtime.h>
#include <cstdint>

#define N_TOK   49
#define C_DIM   256
#define H_NUM   8
#define HD      32
#define B_WIN   4096
#define M_ROWS  (B_WIN * N_TOK)   // 200704

// Scratch (allocation-free rule: __device__ globals)
__device__ float g_qkv[(size_t)B_WIN * H_NUM * 3 * N_TOK * HD];   // 616 MB
__device__ float g_attn[(size_t)M_ROWS * C_DIM];                  // 205 MB (tf32-rounded)
__device__ float g_xcvt[(size_t)M_ROWS * C_DIM];                  // 205 MB (tf32-rounded x)
__device__ float g_wq[768 * 256];                                 // tf32-rounded qkv_w
__device__ float g_wp[256 * 256];                                 // tf32-rounded proj_w
__device__ float g_bm[512 * 2401];                                // bias+mask, 4.9 MB

// ---------------------------------------------------------------------------
__device__ __forceinline__ float to_tf32(float x) {
    uint32_t u;
    asm("cvt.rna.tf32.f32 %0, %1;" : "=r"(u) : "f"(x));
    return __uint_as_float(u);
}

__device__ __forceinline__ void mma_tf32(float c[4], const uint32_t a[4], const uint32_t b[2]) {
    asm volatile(
        "mma.sync.aligned.m16n8k8.row.col.f32.tf32.tf32.f32 "
        "{%0,%1,%2,%3}, {%4,%5,%6,%7}, {%8,%9}, {%0,%1,%2,%3};"
        : "+f"(c[0]), "+f"(c[1]), "+f"(c[2]), "+f"(c[3])
        : "r"(a[0]), "r"(a[1]), "r"(a[2]), "r"(a[3]), "r"(b[0]), "r"(b[1]));
}

__device__ __forceinline__ void cp16(uint32_t smem_addr, const float* gptr) {
    asm volatile("cp.async.cg.shared.global [%0], [%1], 16;"
                 :: "r"(smem_addr), "l"(gptr) : "memory");
}
__device__ __forceinline__ void cp_commit() {
    asm volatile("cp.async.commit_group;" ::: "memory");
}
template<int N>
__device__ __forceinline__ void cp_wait() {
    asm volatile("cp.async.wait_group %0;" :: "n"(N) : "memory");
}

// ---------------------------------------------------------------------------
// Kernel A: tf32 pre-convert (grid-stride over float4)
//   which: 0 -> g_xcvt, 1 -> g_wq, 2 -> g_wp
// ---------------------------------------------------------------------------
__global__ __launch_bounds__(256) void cvt_tf32_kernel(
    const float* __restrict__ src, int n4, int which)
{
    float* dst = (which == 0) ? g_xcvt : (which == 1) ? g_wq : g_wp;
    int idx = blockIdx.x * blockDim.x + threadIdx.x;
    int stride = gridDim.x * blockDim.x;
    for (; idx < n4; idx += stride) {
        float4 v = ((const float4*)src)[idx];
        v.x = to_tf32(v.x); v.y = to_tf32(v.y);
        v.z = to_tf32(v.z); v.w = to_tf32(v.w);
        ((float4*)dst)[idx] = v;
    }
}

// ---------------------------------------------------------------------------
// GEMM: CTA tile 128x128, 4 warps, warp tile 64x64 (2x2 warp grid).
// Per ko-step per warp: 32 mma vs 32 fragment-LDS (was 16:24) -> higher
// tensor duty. cp.async double-buffered 32-deep k-slabs.
// dynamic smem: 2 * (128*36 A + 128*36 B) * 4 = 73728 B (2 CTAs/SM)
// ---------------------------------------------------------------------------
#define SLAB_FLOATS (128 * 36)
#define GEMM_CA_SMEM (4 * SLAB_FLOATS * 4)

template<bool QKV_MODE>
__global__ __launch_bounds__(128) void gemm128_ca(
    const float* __restrict__ bias, float* __restrict__ out)
{
    extern __shared__ float sm[];
    // layout: As[0], As[1], Bs[0], Bs[1] each SLAB_FLOATS
    const uint32_t sm_u32 = (uint32_t)__cvta_generic_to_shared(sm);

    const int tid = threadIdx.x;
    const int mBase = blockIdx.y * 128;   // M on y (large)
    const int nBase = blockIdx.x * 128;   // N on x (small) -> L2 reuse of X
    const float* X = QKV_MODE ? g_xcvt : g_attn;
    const float* W = QKV_MODE ? g_wq : g_wp;

    const int warp = tid >> 5, lane = tid & 31;
    const int wm = (warp & 1) * 64, wn = (warp >> 1) * 64;
    const int g = lane >> 2, t = lane & 3;

    // staging coords: 1024 float4 per operand over 128 threads = 8 each
    const int r0 = tid >> 3;              // 0..15
    const int c0 = (tid & 7) * 4;

    auto issue = [&](int ks, int buf) {
        const float* xrow = X + (size_t)(mBase + r0) * 256 + ks * 32 + c0;
        const float* wrow = W + (size_t)(nBase + r0) * 256 + ks * 32 + c0;
        uint32_t adstA = sm_u32 + (uint32_t)((buf * SLAB_FLOATS + r0 * 36 + c0) * 4);
        uint32_t adstB = sm_u32 + (uint32_t)((2 * SLAB_FLOATS + buf * SLAB_FLOATS + r0 * 36 + c0) * 4);
#pragma unroll
        for (int p = 0; p < 8; p++) {      // rows r0 + p*16
            cp16(adstA + p * 16 * 36 * 4, xrow + (size_t)p * 16 * 256);
            cp16(adstB + p * 16 * 36 * 4, wrow + (size_t)p * 16 * 256);
        }
        cp_commit();
    };

    float acc[4][8][4] = {};   // [mi][ni][4]

    issue(0, 0);
    for (int ks = 0; ks < 8; ks++) {
        const int buf = ks & 1;
        if (ks < 7) issue(ks + 1, buf ^ 1);
        if (ks < 7) cp_wait<1>(); else cp_wait<0>();
        __syncthreads();

        const float* As = sm + buf * SLAB_FLOATS;
        const float* Bs = sm + 2 * SLAB_FLOATS + buf * SLAB_FLOATS;

#pragma unroll
        for (int ko = 0; ko < 32; ko += 8) {
            uint32_t a[4][4], bb[8][2];
#pragma unroll
            for (int mi = 0; mi < 4; mi++) {
                int row = wm + mi * 16 + g;
                a[mi][0] = __float_as_uint(As[row * 36 + ko + t]);
                a[mi][1] = __float_as_uint(As[(row + 8) * 36 + ko + t]);
                a[mi][2] = __float_as_uint(As[row * 36 + ko + t + 4]);
                a[mi][3] = __float_as_uint(As[(row + 8) * 36 + ko + t + 4]);
            }
#pragma unroll
            for (int ni = 0; ni < 8; ni++) {
                int col = wn + ni * 8 + g;
                bb[ni][0] = __float_as_uint(Bs[col * 36 + ko + t]);
                bb[ni][1] = __float_as_uint(Bs[col * 36 + ko + t + 4]);
            }
#pragma unroll
            for (int mi = 0; mi < 4; mi++)
#pragma unroll
                for (int ni = 0; ni < 8; ni++)
                    mma_tf32(acc[mi][ni], a[mi], bb[ni]);
        }
        __syncthreads();   // all warps done reading buf before it is re-issued
    }

    const float qscale = 0.17677669529663687f;
#pragma unroll
    for (int mi = 0; mi < 4; mi++) {
#pragma unroll
        for (int ni = 0; ni < 8; ni++) {
            int gn = nBase + wn + ni * 8 + t * 2;
            float bv0 = bias[gn], bv1 = bias[gn + 1];
            if (QKV_MODE) {
                int which = gn >> 8;
                int h = (gn >> 5) & 7;
                int d = gn & 31;
                float sc = (which == 0) ? qscale : 1.0f;
#pragma unroll
                for (int half = 0; half < 2; half++) {
                    int gm = mBase + wm + mi * 16 + g + half * 8;
                    int b = gm / 49;
                    int r = gm - b * 49;
                    float v0 = (acc[mi][ni][half * 2 + 0] + bv0) * sc;
                    float v1 = (acc[mi][ni][half * 2 + 1] + bv1) * sc;
                    size_t off = ((((size_t)b * 8 + h) * 3 + which) * 49 + r) * 32 + d;
                    *(float2*)(g_qkv + off) = make_float2(v0, v1);
                }
            } else {
#pragma unroll
                for (int half = 0; half < 2; half++) {
                    int gm = mBase + wm + mi * 16 + g + half * 8;
                    float v0 = acc[mi][ni][half * 2 + 0] + bv0;
                    float v1 = acc[mi][ni][half * 2 + 1] + bv1;
                    *(float2*)(out + (size_t)gm * 256 + gn) = make_float2(v0, v1);
                }
            }
        }
    }
}

// ---------------------------------------------------------------------------
// Kernel 0: fuse bias_table + mask -> g_bm[(w*8+h)][i*49+j]
// ---------------------------------------------------------------------------
__global__ __launch_bounds__(256) void fuse_bm_kernel(
    const float* __restrict__ mask, const float* __restrict__ bt)
{
    const int wh = blockIdx.x;          // 0..511
    const int w = wh >> 3, h = wh & 7;
    const float* mw = mask + (size_t)w * 2401;
    float* dst = g_bm + (size_t)wh * 2401;
    for (int idx = threadIdx.x; idx < 2401; idx += 256) {
        int i = idx / 49, j = idx - i * 49;
        int ri = i / 7, ci = i - ri * 7;
        int rj = j / 7, cj = j - rj * 7;
        int bidx = (ri - rj + 6) * 13 + (ci - cj + 6);
        dst[idx] = mw[idx] + bt[bidx * 8 + h];
    }
}

// ---------------------------------------------------------------------------
// Slim tensor-core attention (R6, proven): one CTA per (window, head),
// 64 threads. Output stored tf32-rounded so proj can consume it directly.
// ---------------------------------------------------------------------------
__global__ __launch_bounds__(64) void attn_slim_kernel()
{
    __shared__ float sP[2 * 32 * 60];

    const int bh   = blockIdx.x;
    const int b    = bh >> 3;
    const int h    = bh & 7;
    const int warp = threadIdx.x >> 5;
    const int lane = threadIdx.x & 31;
    const int g = lane >> 2, t = lane & 3;

    const float* qb = g_qkv + (size_t)bh * 3 * 1568;
    const float* kb = qb + 1568;
    const float* vb = qb + 2 * 1568;

    float acc[2][7][4] = {};
#pragma unroll
    for (int kc = 0; kc < 4; kc++) {
        uint32_t a[2][4];
#pragma unroll
        for (int mt = 0; mt < 2; mt++) {
            const float* qr = qb + (warp * 32 + mt * 16 + g) * 32 + kc * 8;
            a[mt][0] = __float_as_uint(to_tf32(qr[t]));
            a[mt][1] = __float_as_uint(to_tf32(qr[8 * 32 + t]));
            a[mt][2] = __float_as_uint(to_tf32(qr[t + 4]));
            a[mt][3] = __float_as_uint(to_tf32(qr[8 * 32 + t + 4]));
        }
#pragma unroll
        for (int tj = 0; tj < 7; tj++) {
            const float* kr = kb + (tj * 8 + g) * 32 + kc * 8;
            uint32_t bb[2];
            bb[0] = __float_as_uint(to_tf32(kr[t]));
            bb[1] = __float_as_uint(to_tf32(kr[t + 4]));
            mma_tf32(acc[0][tj], a[0], bb);
            mma_tf32(acc[1][tj], a[1], bb);
        }
    }

    const float* bmp = g_bm + ((size_t)((b & 63) * 8 + h)) * 2401;
    float* sP_w = sP + warp * 32 * 60;
#pragma unroll
    for (int mt = 0; mt < 2; mt++) {
#pragma unroll
        for (int rh = 0; rh < 2; rh++) {
            int irow = warp * 32 + mt * 16 + g + rh * 8;
            bool vi = (irow < 49);
            const float* bmr = bmp + irow * 49;
            float vals[14];
#pragma unroll
            for (int tj = 0; tj < 7; tj++) {
#pragma unroll
                for (int cc = 0; cc < 2; cc++) {
                    int j = tj * 8 + 2 * t + cc;
                    float s = acc[mt][tj][rh * 2 + cc];
                    s = (vi && j < 49) ? (s + bmr[j]) : -1e30f;
                    vals[tj * 2 + cc] = s;
                }
            }
            float m = vals[0];
#pragma unroll
            for (int u = 1; u < 14; u++) m = fmaxf(m, vals[u]);
            m = fmaxf(m, __shfl_xor_sync(0xffffffffu, m, 1));
            m = fmaxf(m, __shfl_xor_sync(0xffffffffu, m, 2));
            float ssum = 0.f;
#pragma unroll
            for (int u = 0; u < 14; u++) { vals[u] = __expf(vals[u] - m); ssum += vals[u]; }
            ssum += __shfl_xor_sync(0xffffffffu, ssum, 1);
            ssum += __shfl_xor_sync(0xffffffffu, ssum, 2);
            float inv = __frcp_rn(ssum);
            float* prow = sP_w + (mt * 16 + g + rh * 8) * 60;
#pragma unroll
            for (int tj = 0; tj < 7; tj++) {
                float2 p2 = make_float2(to_tf32(vals[tj * 2] * inv),
                                        to_tf32(vals[tj * 2 + 1] * inv));
                *(float2*)(prow + tj * 8 + 2 * t) = p2;
            }
        }
    }
    __syncwarp();

    float pacc[2][4][4] = {};
#pragma unroll
    for (int kc = 0; kc < 7; kc++) {
        uint32_t a[2][4];
#pragma unroll
        for (int mt = 0; mt < 2; mt++) {
            const float* pr = sP_w + (mt * 16 + g) * 60 + kc * 8;
            a[mt][0] = __float_as_uint(pr[t]);
            a[mt][1] = __float_as_uint(pr[8 * 60 + t]);
            a[mt][2] = __float_as_uint(pr[t + 4]);
            a[mt][3] = __float_as_uint(pr[8 * 60 + t + 4]);
        }
        int j0 = kc * 8 + t;
        int j1 = kc * 8 + t + 4;
#pragma unroll
        for (int nt = 0; nt < 4; nt++) {
            int d = nt * 8 + g;
            uint32_t bb[2];
            bb[0] = (j0 < 49) ? __float_as_uint(to_tf32(vb[j0 * 32 + d])) : 0u;
            bb[1] = (j1 < 49) ? __float_as_uint(to_tf32(vb[j1 * 32 + d])) : 0u;
            mma_tf32(pacc[0][nt], a[0], bb);
            mma_tf32(pacc[1][nt], a[1], bb);
        }
    }

    // store rows i < 49, tf32-rounded so proj consumes pre-converted input
#pragma unroll
    for (int mt = 0; mt < 2; mt++) {
#pragma unroll
        for (int rh = 0; rh < 2; rh++) {
            int irow = warp * 32 + mt * 16 + g + rh * 8;
            if (irow < 49) {
                float* op = g_attn + ((size_t)b * 49 + irow) * 256 + h * 32;
#pragma unroll
                for (int nt = 0; nt < 4; nt++) {
                    int d = nt * 8 + 2 * t;
                    *(float2*)(op + d) =
                        make_float2(to_tf32(pacc[mt][nt][rh * 2 + 0]),
                                    to_tf32(pacc[mt][nt][rh * 2 + 1]));
                }
            }
        }
    }
}

// ---------------------------------------------------------------------------
extern "C" void kernel_launch(void* const* d_in, const int* in_sizes, int n_in,
                              void* d_out, int out_size)
{
    const float* x      = (const float*)d_in[0];
    const float* mask   = (const float*)d_in[1];
    const float* qkv_w  = (const float*)d_in[2];
    const float* qkv_b  = (const float*)d_in[3];
    const float* proj_w = (const float*)d_in[4];
    const float* proj_b = (const float*)d_in[5];
    const float* bt     = (const float*)d_in[6];
    float* out = (float*)d_out;

    cudaFuncSetAttribute((const void*)gemm128_ca<true>,
                         cudaFuncAttributeMaxDynamicSharedMemorySize, GEMM_CA_SMEM);
    cudaFuncSetAttribute((const void*)gemm128_ca<false>,
                         cudaFuncAttributeMaxDynamicSharedMemorySize, GEMM_CA_SMEM);

    cvt_tf32_kernel<<<2048, 256>>>(x, M_ROWS * C_DIM / 4, 0);
    cvt_tf32_kernel<<<192, 256>>>(qkv_w, 768 * 256 / 4, 1);
    cvt_tf32_kernel<<<64, 256>>>(proj_w, 256 * 256 / 4, 2);
    fuse_bm_kernel<<<512, 256>>>(mask, bt);

    // grid: x = N-chunks (small), y = M-tiles (1568) -> X reuse via L2
    gemm128_ca<true><<<dim3(6, M_ROWS / 128), 128, GEMM_CA_SMEM>>>(qkv_b, nullptr);
    attn_slim_kernel<<<B_WIN * H_NUM, 64>>>();
    gemm128_ca<false><<<dim3(2, M_ROWS / 128), 128, GEMM_CA_SMEM>>>(proj_b, out);
}

// round 15
// speedup vs baseline: 1.9079x; 1.0731x over previous
#include <cuda_runtime.h>
#include <cstdint>

#define N_TOK   49
#define C_DIM   256
#define H_NUM   8
#define HD      32
#define B_WIN   4096
#define M_ROWS  (B_WIN * N_TOK)   // 200704
#define M16     (M_ROWS / 16)     // 12544

// Scratch (allocation-free rule: __device__ globals)
__device__ float g_qkv[(size_t)B_WIN * H_NUM * 3 * N_TOK * HD];   // 616 MB
__device__ float g_attn[(size_t)M_ROWS * C_DIM];                  // 205 MB (tf32)
__device__ float g_xperm[(size_t)M_ROWS * C_DIM];                 // 205 MB fragment-major x
__device__ float g_wqp[768 * 256];                                // fragment-major qkv_w
__device__ float g_wp[256 * 256];                                 // tf32 row-major proj_w
__device__ float g_bm[512 * 2401];                                // bias+mask, 4.9 MB

// ---------------------------------------------------------------------------
__device__ __forceinline__ float to_tf32(float x) {
    uint32_t u;
    asm("cvt.rna.tf32.f32 %0, %1;" : "=r"(u) : "f"(x));
    return __uint_as_float(u);
}

__device__ __forceinline__ void mma_tf32(float c[4], const uint32_t a[4], const uint32_t b[2]) {
    asm volatile(
        "mma.sync.aligned.m16n8k8.row.col.f32.tf32.tf32.f32 "
        "{%0,%1,%2,%3}, {%4,%5,%6,%7}, {%8,%9}, {%0,%1,%2,%3};"
        : "+f"(c[0]), "+f"(c[1]), "+f"(c[2]), "+f"(c[3])
        : "r"(a[0]), "r"(a[1]), "r"(a[2]), "r"(a[3]), "r"(b[0]), "r"(b[1]));
}

__device__ __forceinline__ void cp16(uint32_t smem_addr, const float* gptr) {
    asm volatile("cp.async.cg.shared.global [%0], [%1], 16;"
                 :: "r"(smem_addr), "l"(gptr) : "memory");
}
__device__ __forceinline__ void cp_commit() {
    asm volatile("cp.async.commit_group;" ::: "memory");
}
template<int N>
__device__ __forceinline__ void cp_wait() {
    asm volatile("cp.async.wait_group %0;" :: "n"(N) : "memory");
}

// ---------------------------------------------------------------------------
// Fragment-major permute of A (x): one thread per (m16, k8, lane) -> float4
//   q order: (g,t),(g+8,t),(g,t+4),(g+8,t+4) == mma a0..a3
// ---------------------------------------------------------------------------
__global__ __launch_bounds__(256) void perm_a_kernel(const float* __restrict__ src)
{
    const int total = M16 * 32 * 32;
    int idx = blockIdx.x * blockDim.x + threadIdx.x;
    int stride = gridDim.x * blockDim.x;
    for (; idx < total; idx += stride) {
        int lane = idx & 31;
        int k8 = (idx >> 5) & 31;
        int m16 = idx >> 10;
        int g = lane >> 2, t = lane & 3;
        size_t r0 = (size_t)(m16 * 16 + g) * 256;
        int c0 = k8 * 8 + t;
        float4 o;
        o.x = to_tf32(src[r0 + c0]);
        o.y = to_tf32(src[r0 + 8 * 256 + c0]);
        o.z = to_tf32(src[r0 + c0 + 4]);
        o.w = to_tf32(src[r0 + 8 * 256 + c0 + 4]);
        ((float4*)g_xperm)[idx] = o;
    }
}

// ---------------------------------------------------------------------------
// Fragment-major permute of B (qkv_w, 768x256): one thread per (n8,k8,lane)
//   p order: (g, t), (g, t+4) == mma b0..b1
// ---------------------------------------------------------------------------
__global__ __launch_bounds__(256) void perm_b_kernel(const float* __restrict__ src)
{
    const int total = 96 * 32 * 32;
    int idx = blockIdx.x * blockDim.x + threadIdx.x;
    int stride = gridDim.x * blockDim.x;
    for (; idx < total; idx += stride) {
        int lane = idx & 31;
        int k8 = (idx >> 5) & 31;
        int n8 = idx >> 10;
        int g = lane >> 2, t = lane & 3;
        size_t n = (size_t)(n8 * 8 + g) * 256;
        int c = k8 * 8 + t;
        float2 o;
        o.x = to_tf32(src[n + c]);
        o.y = to_tf32(src[n + c + 4]);
        ((float2*)g_wqp)[idx] = o;
    }
}

// ---------------------------------------------------------------------------
// Kernel A: plain tf32 convert for proj_w (row-major, proj path unchanged)
// ---------------------------------------------------------------------------
__global__ __launch_bounds__(256) void cvt_wp_kernel(const float* __restrict__ src)
{
    int idx = blockIdx.x * blockDim.x + threadIdx.x;
    int stride = gridDim.x * blockDim.x;
    for (; idx < 256 * 256 / 4; idx += stride) {
        float4 v = ((const float4*)src)[idx];
        v.x = to_tf32(v.x); v.y = to_tf32(v.y);
        v.z = to_tf32(v.z); v.w = to_tf32(v.w);
        ((float4*)g_wp)[idx] = v;
    }
}

// ---------------------------------------------------------------------------
// QKV GEMM, fragment-major operands. CTA tile 128x128, 4 warps (64x64 each).
// Per ko-step per warp: 4 LDS.128 + 8 LDS.64 + 32 mma.
// smem: 2 buf x (A 16KB + B 16KB) = 65536 B
// ---------------------------------------------------------------------------
#define QKV_SMEM 65536

__global__ __launch_bounds__(128) void gemm_qkv_perm(
    const float* __restrict__ bias)
{
    extern __shared__ float sm[];
    // layout: sA[2][4096], sB[2][4096]
    const uint32_t sm_u32 = (uint32_t)__cvta_generic_to_shared(sm);
    const uint32_t sB_u32 = sm_u32 + 2 * 4096 * 4;

    const int tid = threadIdx.x;
    const int mb16 = blockIdx.y * 8;      // 8 m16-blocks per CTA tile
    const int nb8  = blockIdx.x * 16;     // 16 n8-blocks per CTA tile

    const int warp = tid >> 5, lane = tid & 31;
    const int wm16 = (warp & 1) * 4;      // m16-block base within tile
    const int wn8  = (warp >> 1) * 8;     // n8-block base within tile

    // A staging: m16l = tid>>4 (8 groups), 16 threads copy 2KB (128 chunks)
    const int a_m16l = tid >> 4, a_in = tid & 15;
    // B staging: n8l = tid>>3 (16 groups), 8 threads copy 1KB (64 chunks)
    const int b_n8l = tid >> 3, b_in = tid & 7;

    auto issue = [&](int ks, int buf) {
        const float* agm = g_xperm + (size_t)(mb16 + a_m16l) * 4096 + ks * 512;
        uint32_t adst = sm_u32 + (uint32_t)((buf * 4096 + a_m16l * 512) * 4);
#pragma unroll
        for (int j = 0; j < 8; j++) {
            int ch = a_in + j * 16;
            cp16(adst + ch * 16, agm + ch * 4);
        }
        const float* bgm = g_wqp + (size_t)(nb8 + b_n8l) * 2048 + ks * 256;
        uint32_t bdst = sB_u32 + (uint32_t)((buf * 4096 + b_n8l * 256) * 4);
#pragma unroll
        for (int j = 0; j < 8; j++) {
            int ch = b_in + j * 8;
            cp16(bdst + ch * 16, bgm + ch * 4);
        }
        cp_commit();
    };

    float acc[4][8][4] = {};   // [mi][ni][4]

    issue(0, 0);
    for (int ks = 0; ks < 8; ks++) {
        const int buf = ks & 1;
        if (ks < 7) issue(ks + 1, buf ^ 1);
        if (ks < 7) cp_wait<1>(); else cp_wait<0>();
        __syncthreads();

        const float* As = sm + buf * 4096;
        const float* Bs = sm + 2 * 4096 + buf * 4096;

#pragma unroll
        for (int k8l = 0; k8l < 4; k8l++) {
            uint32_t a[4][4], bb[8][2];
#pragma unroll
            for (int mi = 0; mi < 4; mi++) {
                const float4 av = *(const float4*)(As + (wm16 + mi) * 512 + k8l * 128 + lane * 4);
                a[mi][0] = __float_as_uint(av.x);
                a[mi][1] = __float_as_uint(av.y);
                a[mi][2] = __float_as_uint(av.z);
                a[mi][3] = __float_as_uint(av.w);
            }
#pragma unroll
            for (int ni = 0; ni < 8; ni++) {
                const float2 bv = *(const float2*)(Bs + (wn8 + ni) * 256 + k8l * 64 + lane * 2);
                bb[ni][0] = __float_as_uint(bv.x);
                bb[ni][1] = __float_as_uint(bv.y);
            }
#pragma unroll
            for (int mi = 0; mi < 4; mi++)
#pragma unroll
                for (int ni = 0; ni < 8; ni++)
                    mma_tf32(acc[mi][ni], a[mi], bb[ni]);
        }
        __syncthreads();
    }

    // epilogue: scatter into g_qkv with bias + q-scale
    const float qscale = 0.17677669529663687f;
    const int g = lane >> 2, t = lane & 3;
    const int wm = (warp & 1) * 64, wn = (warp >> 1) * 64;
    const int mBase = blockIdx.y * 128, nBase = blockIdx.x * 128;
#pragma unroll
    for (int mi = 0; mi < 4; mi++) {
#pragma unroll
        for (int ni = 0; ni < 8; ni++) {
            int gn = nBase + wn + ni * 8 + t * 2;
            float bv0 = bias[gn], bv1 = bias[gn + 1];
            int which = gn >> 8;
            int h = (gn >> 5) & 7;
            int d = gn & 31;
            float sc = (which == 0) ? qscale : 1.0f;
#pragma unroll
            for (int half = 0; half < 2; half++) {
                int gm = mBase + wm + mi * 16 + g + half * 8;
                int b = gm / 49;
                int r = gm - b * 49;
                float v0 = (acc[mi][ni][half * 2 + 0] + bv0) * sc;
                float v1 = (acc[mi][ni][half * 2 + 1] + bv1) * sc;
                size_t off = ((((size_t)b * 8 + h) * 3 + which) * 49 + r) * 32 + d;
                *(float2*)(g_qkv + off) = make_float2(v0, v1);
            }
        }
    }
}

// ---------------------------------------------------------------------------
// Proj GEMM: unchanged R13 path (A = g_attn row-major, B = g_wp row-major)
// ---------------------------------------------------------------------------
#define SLAB_FLOATS (128 * 36)
#define GEMM_CA_SMEM (4 * SLAB_FLOATS * 4)

__global__ __launch_bounds__(128) void gemm_proj_ca(
    const float* __restrict__ bias, float* __restrict__ out)
{
    extern __shared__ float sm[];
    const uint32_t sm_u32 = (uint32_t)__cvta_generic_to_shared(sm);

    const int tid = threadIdx.x;
    const int mBase = blockIdx.y * 128;
    const int nBase = blockIdx.x * 128;
    const float* X = g_attn;
    const float* W = g_wp;

    const int warp = tid >> 5, lane = tid & 31;
    const int wm = (warp & 1) * 64, wn = (warp >> 1) * 64;
    const int g = lane >> 2, t = lane & 3;

    const int r0 = tid >> 3;
    const int c0 = (tid & 7) * 4;

    auto issue = [&](int ks, int buf) {
        const float* xrow = X + (size_t)(mBase + r0) * 256 + ks * 32 + c0;
        const float* wrow = W + (size_t)(nBase + r0) * 256 + ks * 32 + c0;
        uint32_t adstA = sm_u32 + (uint32_t)((buf * SLAB_FLOATS + r0 * 36 + c0) * 4);
        uint32_t adstB = sm_u32 + (uint32_t)((2 * SLAB_FLOATS + buf * SLAB_FLOATS + r0 * 36 + c0) * 4);
#pragma unroll
        for (int p = 0; p < 8; p++) {
            cp16(adstA + p * 16 * 36 * 4, xrow + (size_t)p * 16 * 256);
            cp16(adstB + p * 16 * 36 * 4, wrow + (size_t)p * 16 * 256);
        }
        cp_commit();
    };

    float acc[4][8][4] = {};

    issue(0, 0);
    for (int ks = 0; ks < 8; ks++) {
        const int buf = ks & 1;
        if (ks < 7) issue(ks + 1, buf ^ 1);
        if (ks < 7) cp_wait<1>(); else cp_wait<0>();
        __syncthreads();

        const float* As = sm + buf * SLAB_FLOATS;
        const float* Bs = sm + 2 * SLAB_FLOATS + buf * SLAB_FLOATS;

#pragma unroll
        for (int ko = 0; ko < 32; ko += 8) {
            uint32_t a[4][4], bb[8][2];
#pragma unroll
            for (int mi = 0; mi < 4; mi++) {
                int row = wm + mi * 16 + g;
                a[mi][0] = __float_as_uint(As[row * 36 + ko + t]);
                a[mi][1] = __float_as_uint(As[(row + 8) * 36 + ko + t]);
                a[mi][2] = __float_as_uint(As[row * 36 + ko + t + 4]);
                a[mi][3] = __float_as_uint(As[(row + 8) * 36 + ko + t + 4]);
            }
#pragma unroll
            for (int ni = 0; ni < 8; ni++) {
                int col = wn + ni * 8 + g;
                bb[ni][0] = __float_as_uint(Bs[col * 36 + ko + t]);
                bb[ni][1] = __float_as_uint(Bs[col * 36 + ko + t + 4]);
            }
#pragma unroll
            for (int mi = 0; mi < 4; mi++)
#pragma unroll
                for (int ni = 0; ni < 8; ni++)
                    mma_tf32(acc[mi][ni], a[mi], bb[ni]);
        }
        __syncthreads();
    }

#pragma unroll
    for (int mi = 0; mi < 4; mi++) {
#pragma unroll
        for (int ni = 0; ni < 8; ni++) {
            int gn = nBase + wn + ni * 8 + t * 2;
            float bv0 = bias[gn], bv1 = bias[gn + 1];
#pragma unroll
            for (int half = 0; half < 2; half++) {
                int gm = mBase + wm + mi * 16 + g + half * 8;
                float v0 = acc[mi][ni][half * 2 + 0] + bv0;
                float v1 = acc[mi][ni][half * 2 + 1] + bv1;
                *(float2*)(out + (size_t)gm * 256 + gn) = make_float2(v0, v1);
            }
        }
    }
}

// ---------------------------------------------------------------------------
// Kernel 0: fuse bias_table + mask -> g_bm[(w*8+h)][i*49+j]
// ---------------------------------------------------------------------------
__global__ __launch_bounds__(256) void fuse_bm_kernel(
    const float* __restrict__ mask, const float* __restrict__ bt)
{
    const int wh = blockIdx.x;
    const int w = wh >> 3, h = wh & 7;
    const float* mw = mask + (size_t)w * 2401;
    float* dst = g_bm + (size_t)wh * 2401;
    for (int idx = threadIdx.x; idx < 2401; idx += 256) {
        int i = idx / 49, j = idx - i * 49;
        int ri = i / 7, ci = i - ri * 7;
        int rj = j / 7, cj = j - rj * 7;
        int bidx = (ri - rj + 6) * 13 + (ci - cj + 6);
        dst[idx] = mw[idx] + bt[bidx * 8 + h];
    }
}

// ---------------------------------------------------------------------------
// Slim tensor-core attention (proven): one CTA per (window, head), 64 thr.
// ---------------------------------------------------------------------------
__global__ __launch_bounds__(64) void attn_slim_kernel()
{
    __shared__ float sP[2 * 32 * 60];

    const int bh   = blockIdx.x;
    const int b    = bh >> 3;
    const int h    = bh & 7;
    const int warp = threadIdx.x >> 5;
    const int lane = threadIdx.x & 31;
    const int g = lane >> 2, t = lane & 3;

    const float* qb = g_qkv + (size_t)bh * 3 * 1568;
    const float* kb = qb + 1568;
    const float* vb = qb + 2 * 1568;

    float acc[2][7][4] = {};
#pragma unroll
    for (int kc = 0; kc < 4; kc++) {
        uint32_t a[2][4];
#pragma unroll
        for (int mt = 0; mt < 2; mt++) {
            const float* qr = qb + (warp * 32 + mt * 16 + g) * 32 + kc * 8;
            a[mt][0] = __float_as_uint(to_tf32(qr[t]));
            a[mt][1] = __float_as_uint(to_tf32(qr[8 * 32 + t]));
            a[mt][2] = __float_as_uint(to_tf32(qr[t + 4]));
            a[mt][3] = __float_as_uint(to_tf32(qr[8 * 32 + t + 4]));
        }
#pragma unroll
        for (int tj = 0; tj < 7; tj++) {
            const float* kr = kb + (tj * 8 + g) * 32 + kc * 8;
            uint32_t bb[2];
            bb[0] = __float_as_uint(to_tf32(kr[t]));
            bb[1] = __float_as_uint(to_tf32(kr[t + 4]));
            mma_tf32(acc[0][tj], a[0], bb);
            mma_tf32(acc[1][tj], a[1], bb);
        }
    }

    const float* bmp = g_bm + ((size_t)((b & 63) * 8 + h)) * 2401;
    float* sP_w = sP + warp * 32 * 60;
#pragma unroll
    for (int mt = 0; mt < 2; mt++) {
#pragma unroll
        for (int rh = 0; rh < 2; rh++) {
            int irow = warp * 32 + mt * 16 + g + rh * 8;
            bool vi = (irow < 49);
            const float* bmr = bmp + irow * 49;
            float vals[14];
#pragma unroll
            for (int tj = 0; tj < 7; tj++) {
#pragma unroll
                for (int cc = 0; cc < 2; cc++) {
                    int j = tj * 8 + 2 * t + cc;
                    float s = acc[mt][tj][rh * 2 + cc];
                    s = (vi && j < 49) ? (s + bmr[j]) : -1e30f;
                    vals[tj * 2 + cc] = s;
                }
            }
            float m = vals[0];
#pragma unroll
            for (int u = 1; u < 14; u++) m = fmaxf(m, vals[u]);
            m = fmaxf(m, __shfl_xor_sync(0xffffffffu, m, 1));
            m = fmaxf(m, __shfl_xor_sync(0xffffffffu, m, 2));
            float ssum = 0.f;
#pragma unroll
            for (int u = 0; u < 14; u++) { vals[u] = __expf(vals[u] - m); ssum += vals[u]; }
            ssum += __shfl_xor_sync(0xffffffffu, ssum, 1);
            ssum += __shfl_xor_sync(0xffffffffu, ssum, 2);
            float inv = __frcp_rn(ssum);
            float* prow = sP_w + (mt * 16 + g + rh * 8) * 60;
#pragma unroll
            for (int tj = 0; tj < 7; tj++) {
                float2 p2 = make_float2(to_tf32(vals[tj * 2] * inv),
                                        to_tf32(vals[tj * 2 + 1] * inv));
                *(float2*)(prow + tj * 8 + 2 * t) = p2;
            }
        }
    }
    __syncwarp();

    float pacc[2][4][4] = {};
#pragma unroll
    for (int kc = 0; kc < 7; kc++) {
        uint32_t a[2][4];
#pragma unroll
        for (int mt = 0; mt < 2; mt++) {
            const float* pr = sP_w + (mt * 16 + g) * 60 + kc * 8;
            a[mt][0] = __float_as_uint(pr[t]);
            a[mt][1] = __float_as_uint(pr[8 * 60 + t]);
            a[mt][2] = __float_as_uint(pr[t + 4]);
            a[mt][3] = __float_as_uint(pr[8 * 60 + t + 4]);
        }
        int j0 = kc * 8 + t;
        int j1 = kc * 8 + t + 4;
#pragma unroll
        for (int nt = 0; nt < 4; nt++) {
            int d = nt * 8 + g;
            uint32_t bb[2];
            bb[0] = (j0 < 49) ? __float_as_uint(to_tf32(vb[j0 * 32 + d])) : 0u;
            bb[1] = (j1 < 49) ? __float_as_uint(to_tf32(vb[j1 * 32 + d])) : 0u;
            mma_tf32(pacc[0][nt], a[0], bb);
            mma_tf32(pacc[1][nt], a[1], bb);
        }
    }

#pragma unroll
    for (int mt = 0; mt < 2; mt++) {
#pragma unroll
        for (int rh = 0; rh < 2; rh++) {
            int irow = warp * 32 + mt * 16 + g + rh * 8;
            if (irow < 49) {
                float* op = g_attn + ((size_t)b * 49 + irow) * 256 + h * 32;
#pragma unroll
                for (int nt = 0; nt < 4; nt++) {
                    int d = nt * 8 + 2 * t;
                    *(float2*)(op + d) =
                        make_float2(to_tf32(pacc[mt][nt][rh * 2 + 0]),
                                    to_tf32(pacc[mt][nt][rh * 2 + 1]));
                }
            }
        }
    }
}

// ---------------------------------------------------------------------------
extern "C" void kernel_launch(void* const* d_in, const int* in_sizes, int n_in,
                              void* d_out, int out_size)
{
    const float* x      = (const float*)d_in[0];
    const float* mask   = (const float*)d_in[1];
    const float* qkv_w  = (const float*)d_in[2];
    const float* qkv_b  = (const float*)d_in[3];
    const float* proj_w = (const float*)d_in[4];
    const float* proj_b = (const float*)d_in[5];
    const float* bt     = (const float*)d_in[6];
    float* out = (float*)d_out;

    cudaFuncSetAttribute((const void*)gemm_qkv_perm,
                         cudaFuncAttributeMaxDynamicSharedMemorySize, QKV_SMEM);
    cudaFuncSetAttribute((const void*)gemm_proj_ca,
                         cudaFuncAttributeMaxDynamicSharedMemorySize, GEMM_CA_SMEM);

    perm_a_kernel<<<2048, 256>>>(x);
    perm_b_kernel<<<384, 256>>>(qkv_w);
    cvt_wp_kernel<<<64, 256>>>(proj_w);
    fuse_bm_kernel<<<512, 256>>>(mask, bt);

    gemm_qkv_perm<<<dim3(6, M_ROWS / 128), 128, QKV_SMEM>>>(qkv_b);
    attn_slim_kernel<<<B_WIN * H_NUM, 64>>>();
    gemm_proj_ca<<<dim3(2, M_ROWS / 128), 128, GEMM_CA_SMEM>>>(proj_b, out);
}

// round 16
// speedup vs baseline: 1.9842x; 1.0400x over previous
#include <cuda_runtime.h>
#include <cstdint>

#define N_TOK   49
#define C_DIM   256
#define H_NUM   8
#define HD      32
#define B_WIN   4096
#define M_ROWS  (B_WIN * N_TOK)   // 200704
#define M16     (M_ROWS / 16)     // 12544
#define BM_STRIDE 56              // padded row (even -> 8B-aligned float2)
#define BM_SLAB  (N_TOK * BM_STRIDE)   // 2744

// Scratch (allocation-free rule: __device__ globals)
__device__ float g_qkv[(size_t)B_WIN * H_NUM * 3 * N_TOK * HD];   // 616 MB (tf32)
__device__ float g_attn[(size_t)M_ROWS * C_DIM];                  // 205 MB (tf32)
__device__ float g_xperm[(size_t)M_ROWS * C_DIM];                 // fragment-major x
__device__ float g_wqp[768 * 256];                                // fragment-major qkv_w
__device__ float g_wpp[256 * 256];                                // fragment-major proj_w
__device__ float g_bm[512 * BM_SLAB];                             // bias+mask, padded

// ---------------------------------------------------------------------------
__device__ __forceinline__ float to_tf32(float x) {
    uint32_t u;
    asm("cvt.rna.tf32.f32 %0, %1;" : "=r"(u) : "f"(x));
    return __uint_as_float(u);
}

__device__ __forceinline__ void mma_tf32(float c[4], const uint32_t a[4], const uint32_t b[2]) {
    asm volatile(
        "mma.sync.aligned.m16n8k8.row.col.f32.tf32.tf32.f32 "
        "{%0,%1,%2,%3}, {%4,%5,%6,%7}, {%8,%9}, {%0,%1,%2,%3};"
        : "+f"(c[0]), "+f"(c[1]), "+f"(c[2]), "+f"(c[3])
        : "r"(a[0]), "r"(a[1]), "r"(a[2]), "r"(a[3]), "r"(b[0]), "r"(b[1]));
}

__device__ __forceinline__ void cp16(uint32_t smem_addr, const float* gptr) {
    asm volatile("cp.async.cg.shared.global [%0], [%1], 16;"
                 :: "r"(smem_addr), "l"(gptr) : "memory");
}
__device__ __forceinline__ void cp_commit() {
    asm volatile("cp.async.commit_group;" ::: "memory");
}
template<int N>
__device__ __forceinline__ void cp_wait() {
    asm volatile("cp.async.wait_group %0;" :: "n"(N) : "memory");
}

// ---------------------------------------------------------------------------
// Fragment-major permute of A (x): one thread per (m16, k8, lane) -> float4
// ---------------------------------------------------------------------------
__global__ __launch_bounds__(256) void perm_a_kernel(const float* __restrict__ src)
{
    const int total = M16 * 32 * 32;
    int idx = blockIdx.x * blockDim.x + threadIdx.x;
    int stride = gridDim.x * blockDim.x;
    for (; idx < total; idx += stride) {
        int lane = idx & 31;
        int k8 = (idx >> 5) & 31;
        int m16 = idx >> 10;
        int g = lane >> 2, t = lane & 3;
        size_t r0 = (size_t)(m16 * 16 + g) * 256;
        int c0 = k8 * 8 + t;
        float4 o;
        o.x = to_tf32(src[r0 + c0]);
        o.y = to_tf32(src[r0 + 8 * 256 + c0]);
        o.z = to_tf32(src[r0 + c0 + 4]);
        o.w = to_tf32(src[r0 + 8 * 256 + c0 + 4]);
        ((float4*)g_xperm)[idx] = o;
    }
}

// ---------------------------------------------------------------------------
// Fragment-major permute of B weights: one thread per (n8,k8,lane) -> float2
//   which: 0 -> g_wqp (768x256), 1 -> g_wpp (256x256)
// ---------------------------------------------------------------------------
__global__ __launch_bounds__(256) void perm_b_kernel(
    const float* __restrict__ src, int n8_count, int which)
{
    float* dst = (which == 0) ? g_wqp : g_wpp;
    const int total = n8_count * 32 * 32;
    int idx = blockIdx.x * blockDim.x + threadIdx.x;
    int stride = gridDim.x * blockDim.x;
    for (; idx < total; idx += stride) {
        int lane = idx & 31;
        int k8 = (idx >> 5) & 31;
        int n8 = idx >> 10;
        int g = lane >> 2, t = lane & 3;
        size_t n = (size_t)(n8 * 8 + g) * 256;
        int c = k8 * 8 + t;
        float2 o;
        o.x = to_tf32(src[n + c]);
        o.y = to_tf32(src[n + c + 4]);
        ((float2*)dst)[idx] = o;
    }
}

// ---------------------------------------------------------------------------
// QKV GEMM, fragment-major operands (proven R15). Epilogue now stores
// tf32-rounded values so attention needs no cvt.
// ---------------------------------------------------------------------------
#define QKV_SMEM 65536

__global__ __launch_bounds__(128) void gemm_qkv_perm(
    const float* __restrict__ bias)
{
    extern __shared__ float sm[];
    const uint32_t sm_u32 = (uint32_t)__cvta_generic_to_shared(sm);
    const uint32_t sB_u32 = sm_u32 + 2 * 4096 * 4;

    const int tid = threadIdx.x;
    const int mb16 = blockIdx.y * 8;
    const int nb8  = blockIdx.x * 16;

    const int warp = tid >> 5, lane = tid & 31;
    const int wm16 = (warp & 1) * 4;
    const int wn8  = (warp >> 1) * 8;

    const int a_m16l = tid >> 4, a_in = tid & 15;
    const int b_n8l = tid >> 3, b_in = tid & 7;

    auto issue = [&](int ks, int buf) {
        const float* agm = g_xperm + (size_t)(mb16 + a_m16l) * 4096 + ks * 512;
        uint32_t adst = sm_u32 + (uint32_t)((buf * 4096 + a_m16l * 512) * 4);
#pragma unroll
        for (int j = 0; j < 8; j++) {
            int ch = a_in + j * 16;
            cp16(adst + ch * 16, agm + ch * 4);
        }
        const float* bgm = g_wqp + (size_t)(nb8 + b_n8l) * 2048 + ks * 256;
        uint32_t bdst = sB_u32 + (uint32_t)((buf * 4096 + b_n8l * 256) * 4);
#pragma unroll
        for (int j = 0; j < 8; j++) {
            int ch = b_in + j * 8;
            cp16(bdst + ch * 16, bgm + ch * 4);
        }
        cp_commit();
    };

    float acc[4][8][4] = {};

    issue(0, 0);
    for (int ks = 0; ks < 8; ks++) {
        const int buf = ks & 1;
        if (ks < 7) issue(ks + 1, buf ^ 1);
        if (ks < 7) cp_wait<1>(); else cp_wait<0>();
        __syncthreads();

        const float* As = sm + buf * 4096;
        const float* Bs = sm + 2 * 4096 + buf * 4096;

#pragma unroll
        for (int k8l = 0; k8l < 4; k8l++) {
            uint32_t a[4][4], bb[8][2];
#pragma unroll
            for (int mi = 0; mi < 4; mi++) {
                const float4 av = *(const float4*)(As + (wm16 + mi) * 512 + k8l * 128 + lane * 4);
                a[mi][0] = __float_as_uint(av.x);
                a[mi][1] = __float_as_uint(av.y);
                a[mi][2] = __float_as_uint(av.z);
                a[mi][3] = __float_as_uint(av.w);
            }
#pragma unroll
            for (int ni = 0; ni < 8; ni++) {
                const float2 bv = *(const float2*)(Bs + (wn8 + ni) * 256 + k8l * 64 + lane * 2);
                bb[ni][0] = __float_as_uint(bv.x);
                bb[ni][1] = __float_as_uint(bv.y);
            }
#pragma unroll
            for (int mi = 0; mi < 4; mi++)
#pragma unroll
                for (int ni = 0; ni < 8; ni++)
                    mma_tf32(acc[mi][ni], a[mi], bb[ni]);
        }
        __syncthreads();
    }

    // epilogue: scatter tf32-rounded values into g_qkv
    const float qscale = 0.17677669529663687f;
    const int g = lane >> 2, t = lane & 3;
    const int wm = (warp & 1) * 64, wn = (warp >> 1) * 64;
    const int mBase = blockIdx.y * 128, nBase = blockIdx.x * 128;
#pragma unroll
    for (int mi = 0; mi < 4; mi++) {
#pragma unroll
        for (int ni = 0; ni < 8; ni++) {
            int gn = nBase + wn + ni * 8 + t * 2;
            float bv0 = bias[gn], bv1 = bias[gn + 1];
            int which = gn >> 8;
            int h = (gn >> 5) & 7;
            int d = gn & 31;
            float sc = (which == 0) ? qscale : 1.0f;
#pragma unroll
            for (int half = 0; half < 2; half++) {
                int gm = mBase + wm + mi * 16 + g + half * 8;
                int b = gm / 49;
                int r = gm - b * 49;
                float v0 = to_tf32((acc[mi][ni][half * 2 + 0] + bv0) * sc);
                float v1 = to_tf32((acc[mi][ni][half * 2 + 1] + bv1) * sc);
                size_t off = ((((size_t)b * 8 + h) * 3 + which) * 49 + r) * 32 + d;
                *(float2*)(g_qkv + off) = make_float2(v0, v1);
            }
        }
    }
}

// ---------------------------------------------------------------------------
// Proj GEMM: A = g_attn row-major slabs (36-stride), B = g_wpp fragment-major
// smem: A 2x128x36x4 = 36864 + B 2x4096x4 = 32768 -> 69632 B
// ---------------------------------------------------------------------------
#define PROJ_SMEM (36864 + 32768)

__global__ __launch_bounds__(128) void gemm_proj_fm(
    const float* __restrict__ bias, float* __restrict__ out)
{
    extern __shared__ float sm[];
    const uint32_t sm_u32 = (uint32_t)__cvta_generic_to_shared(sm);
    const uint32_t sB_u32 = sm_u32 + 2 * 128 * 36 * 4;

    const int tid = threadIdx.x;
    const int mBase = blockIdx.y * 128;
    const int nb8  = blockIdx.x * 16;
    const int nBase = blockIdx.x * 128;

    const int warp = tid >> 5, lane = tid & 31;
    const int wm = (warp & 1) * 64, wn8 = (warp >> 1) * 8;
    const int g = lane >> 2, t = lane & 3;

    const int r0 = tid >> 3;              // 0..15
    const int c0 = (tid & 7) * 4;
    const int b_n8l = tid >> 3, b_in = tid & 7;

    auto issue = [&](int ks, int buf) {
        const float* xrow = g_attn + (size_t)(mBase + r0) * 256 + ks * 32 + c0;
        uint32_t adst = sm_u32 + (uint32_t)((buf * 128 * 36 + r0 * 36 + c0) * 4);
#pragma unroll
        for (int p = 0; p < 8; p++) {
            cp16(adst + p * 16 * 36 * 4, xrow + (size_t)p * 16 * 256);
        }
        const float* bgm = g_wpp + (size_t)(nb8 + b_n8l) * 2048 + ks * 256;
        uint32_t bdst = sB_u32 + (uint32_t)((buf * 4096 + b_n8l * 256) * 4);
#pragma unroll
        for (int j = 0; j < 8; j++) {
            int ch = b_in + j * 8;
            cp16(bdst + ch * 16, bgm + ch * 4);
        }
        cp_commit();
    };

    float acc[4][8][4] = {};

    issue(0, 0);
    for (int ks = 0; ks < 8; ks++) {
        const int buf = ks & 1;
        if (ks < 7) issue(ks + 1, buf ^ 1);
        if (ks < 7) cp_wait<1>(); else cp_wait<0>();
        __syncthreads();

        const float* As = sm + buf * 128 * 36;
        const float* Bs = sm + 2 * 128 * 36 + buf * 4096;

#pragma unroll
        for (int k8l = 0; k8l < 4; k8l++) {
            const int ko = k8l * 8;
            uint32_t a[4][4], bb[8][2];
#pragma unroll
            for (int mi = 0; mi < 4; mi++) {
                int row = wm + mi * 16 + g;
                a[mi][0] = __float_as_uint(As[row * 36 + ko + t]);
                a[mi][1] = __float_as_uint(As[(row + 8) * 36 + ko + t]);
                a[mi][2] = __float_as_uint(As[row * 36 + ko + t + 4]);
                a[mi][3] = __float_as_uint(As[(row + 8) * 36 + ko + t + 4]);
            }
#pragma unroll
            for (int ni = 0; ni < 8; ni++) {
                const float2 bv = *(const float2*)(Bs + (wn8 + ni) * 256 + k8l * 64 + lane * 2);
                bb[ni][0] = __float_as_uint(bv.x);
                bb[ni][1] = __float_as_uint(bv.y);
            }
#pragma unroll
            for (int mi = 0; mi < 4; mi++)
#pragma unroll
                for (int ni = 0; ni < 8; ni++)
                    mma_tf32(acc[mi][ni], a[mi], bb[ni]);
        }
        __syncthreads();
    }

    const int wn = (warp >> 1) * 64;
#pragma unroll
    for (int mi = 0; mi < 4; mi++) {
#pragma unroll
        for (int ni = 0; ni < 8; ni++) {
            int gn = nBase + wn + ni * 8 + t * 2;
            float bv0 = bias[gn], bv1 = bias[gn + 1];
#pragma unroll
            for (int half = 0; half < 2; half++) {
                int gm = mBase + wm + mi * 16 + g + half * 8;
                float v0 = acc[mi][ni][half * 2 + 0] + bv0;
                float v1 = acc[mi][ni][half * 2 + 1] + bv1;
                *(float2*)(out + (size_t)gm * 256 + gn) = make_float2(v0, v1);
            }
        }
    }
}

// ---------------------------------------------------------------------------
// Kernel 0: fuse bias_table + mask -> g_bm[(w*8+h)][i*56+j]  (padded rows)
// ---------------------------------------------------------------------------
__global__ __launch_bounds__(256) void fuse_bm_kernel(
    const float* __restrict__ mask, const float* __restrict__ bt)
{
    const int wh = blockIdx.x;
    const int w = wh >> 3, h = wh & 7;
    const float* mw = mask + (size_t)w * 2401;
    float* dst = g_bm + (size_t)wh * BM_SLAB;
    for (int idx = threadIdx.x; idx < 2401; idx += 256) {
        int i = idx / 49, j = idx - i * 49;
        int ri = i / 7, ci = i - ri * 7;
        int rj = j / 7, cj = j - rj * 7;
        int bidx = (ri - rj + 6) * 13 + (ci - cj + 6);
        dst[i * BM_STRIDE + j] = mw[idx] + bt[bidx * 8 + h];
    }
}

// ---------------------------------------------------------------------------
// Slim tensor-core attention: inputs already tf32 -> no cvt on loads;
// bias+mask via float2 loads from padded g_bm.
// ---------------------------------------------------------------------------
__global__ __launch_bounds__(64) void attn_slim_kernel()
{
    __shared__ float sP[2 * 32 * 60];

    const int bh   = blockIdx.x;
    const int b    = bh >> 3;
    const int h    = bh & 7;
    const int warp = threadIdx.x >> 5;
    const int lane = threadIdx.x & 31;
    const int g = lane >> 2, t = lane & 3;

    const float* qb = g_qkv + (size_t)bh * 3 * 1568;
    const float* kb = qb + 1568;
    const float* vb = qb + 2 * 1568;

    float acc[2][7][4] = {};
#pragma unroll
    for (int kc = 0; kc < 4; kc++) {
        uint32_t a[2][4];
#pragma unroll
        for (int mt = 0; mt < 2; mt++) {
            const float* qr = qb + (warp * 32 + mt * 16 + g) * 32 + kc * 8;
            a[mt][0] = __float_as_uint(qr[t]);
            a[mt][1] = __float_as_uint(qr[8 * 32 + t]);
            a[mt][2] = __float_as_uint(qr[t + 4]);
            a[mt][3] = __float_as_uint(qr[8 * 32 + t + 4]);
        }
#pragma unroll
        for (int tj = 0; tj < 7; tj++) {
            const float* kr = kb + (tj * 8 + g) * 32 + kc * 8;
            uint32_t bb[2];
            bb[0] = __float_as_uint(kr[t]);
            bb[1] = __float_as_uint(kr[t + 4]);
            mma_tf32(acc[0][tj], a[0], bb);
            mma_tf32(acc[1][tj], a[1], bb);
        }
    }

    const float* bmp = g_bm + ((size_t)((b & 63) * 8 + h)) * BM_SLAB;
    float* sP_w = sP + warp * 32 * 60;
#pragma unroll
    for (int mt = 0; mt < 2; mt++) {
#pragma unroll
        for (int rh = 0; rh < 2; rh++) {
            int irow = warp * 32 + mt * 16 + g + rh * 8;
            bool vi = (irow < 49);
            const float* bmr = bmp + irow * BM_STRIDE;
            float vals[14];
#pragma unroll
            for (int tj = 0; tj < 7; tj++) {
                float2 bm2 = vi ? *(const float2*)(bmr + tj * 8 + 2 * t)
                                : make_float2(0.f, 0.f);
#pragma unroll
                for (int cc = 0; cc < 2; cc++) {
                    int j = tj * 8 + 2 * t + cc;
                    float s = acc[mt][tj][rh * 2 + cc];
                    s = (vi && j < 49) ? (s + (cc ? bm2.y : bm2.x)) : -1e30f;
                    vals[tj * 2 + cc] = s;
                }
            }
            float m = vals[0];
#pragma unroll
            for (int u = 1; u < 14; u++) m = fmaxf(m, vals[u]);
            m = fmaxf(m, __shfl_xor_sync(0xffffffffu, m, 1));
            m = fmaxf(m, __shfl_xor_sync(0xffffffffu, m, 2));
            float ssum = 0.f;
#pragma unroll
            for (int u = 0; u < 14; u++) { vals[u] = __expf(vals[u] - m); ssum += vals[u]; }
            ssum += __shfl_xor_sync(0xffffffffu, ssum, 1);
            ssum += __shfl_xor_sync(0xffffffffu, ssum, 2);
            float inv = __frcp_rn(ssum);
            float* prow = sP_w + (mt * 16 + g + rh * 8) * 60;
#pragma unroll
            for (int tj = 0; tj < 7; tj++) {
                float2 p2 = make_float2(to_tf32(vals[tj * 2] * inv),
                                        to_tf32(vals[tj * 2 + 1] * inv));
                *(float2*)(prow + tj * 8 + 2 * t) = p2;
            }
        }
    }
    __syncwarp();

    float pacc[2][4][4] = {};
#pragma unroll
    for (int kc = 0; kc < 7; kc++) {
        uint32_t a[2][4];
#pragma unroll
        for (int mt = 0; mt < 2; mt++) {
            const float* pr = sP_w + (mt * 16 + g) * 60 + kc * 8;
            a[mt][0] = __float_as_uint(pr[t]);
            a[mt][1] = __float_as_uint(pr[8 * 60 + t]);
            a[mt][2] = __float_as_uint(pr[t + 4]);
            a[mt][3] = __float_as_uint(pr[8 * 60 + t + 4]);
        }
        int j0 = kc * 8 + t;
        int j1 = kc * 8 + t + 4;
#pragma unroll
        for (int nt = 0; nt < 4; nt++) {
            int d = nt * 8 + g;
            uint32_t bb[2];
            bb[0] = (j0 < 49) ? __float_as_uint(vb[j0 * 32 + d]) : 0u;
            bb[1] = (j1 < 49) ? __float_as_uint(vb[j1 * 32 + d]) : 0u;
            mma_tf32(pacc[0][nt], a[0], bb);
            mma_tf32(pacc[1][nt], a[1], bb);
        }
    }

    // store rows i < 49, tf32-rounded so proj consumes pre-converted input
#pragma unroll
    for (int mt = 0; mt < 2; mt++) {
#pragma unroll
        for (int rh = 0; rh < 2; rh++) {
            int irow = warp * 32 + mt * 16 + g + rh * 8;
            if (irow < 49) {
                float* op = g_attn + ((size_t)b * 49 + irow) * 256 + h * 32;
#pragma unroll
                for (int nt = 0; nt < 4; nt++) {
                    int d = nt * 8 + 2 * t;
                    *(float2*)(op + d) =
                        make_float2(to_tf32(pacc[mt][nt][rh * 2 + 0]),
                                    to_tf32(pacc[mt][nt][rh * 2 + 1]));
                }
            }
        }
    }
}

// ---------------------------------------------------------------------------
extern "C" void kernel_launch(void* const* d_in, const int* in_sizes, int n_in,
                              void* d_out, int out_size)
{
    const float* x      = (const float*)d_in[0];
    const float* mask   = (const float*)d_in[1];
    const float* qkv_w  = (const float*)d_in[2];
    const float* qkv_b  = (const float*)d_in[3];
    const float* proj_w = (const float*)d_in[4];
    const float* proj_b = (const float*)d_in[5];
    const float* bt     = (const float*)d_in[6];
    float* out = (float*)d_out;

    cudaFuncSetAttribute((const void*)gemm_qkv_perm,
                         cudaFuncAttributeMaxDynamicSharedMemorySize, QKV_SMEM);
    cudaFuncSetAttribute((const void*)gemm_proj_fm,
                         cudaFuncAttributeMaxDynamicSharedMemorySize, PROJ_SMEM);

    perm_a_kernel<<<2048, 256>>>(x);
    perm_b_kernel<<<384, 256>>>(qkv_w, 96, 0);
    perm_b_kernel<<<128, 256>>>(proj_w, 32, 1);
    fuse_bm_kernel<<<512, 256>>>(mask, bt);

    gemm_qkv_perm<<<dim3(6, M_ROWS / 128), 128, QKV_SMEM>>>(qkv_b);
    attn_slim_kernel<<<B_WIN * H_NUM, 64>>>();
    gemm_proj_fm<<<dim3(2, M_ROWS / 128), 128, PROJ_SMEM>>>(proj_b, out);
}

// round 17
// speedup vs baseline: 2.0624x; 1.0394x over previous
#include <cuda_runtime.h>
#include <cstdint>

#define N_TOK   49
#define C_DIM   256
#define H_NUM   8
#define HD      32
#define B_WIN   4096
#define M_ROWS  (B_WIN * N_TOK)   // 200704
#define M16     (M_ROWS / 16)     // 12544
#define BM_STRIDE 56
#define BM_SLAB  (N_TOK * BM_STRIDE)   // 2744

// per-(b,h) slab in g_qkv: q row-major [49][32] | kfrag [7*4][64] | vfrag [4*7][64]
#define QKV_SLAB 5152
#define KF_OFF   1568
#define VF_OFF   3360

// Scratch (allocation-free rule: __device__ globals)
__device__ float g_qkv[(size_t)B_WIN * H_NUM * QKV_SLAB];         // 676 MB (tf32)
__device__ float g_attn[(size_t)M_ROWS * C_DIM];                  // 205 MB (tf32)
__device__ float g_xperm[(size_t)M_ROWS * C_DIM];                 // fragment-major x
__device__ float g_wqp[768 * 256];                                // fragment-major qkv_w
__device__ float g_wpp[256 * 256];                                // fragment-major proj_w
__device__ float g_bm[512 * BM_SLAB];                             // bias+mask, padded

// ---------------------------------------------------------------------------
__device__ __forceinline__ float to_tf32(float x) {
    uint32_t u;
    asm("cvt.rna.tf32.f32 %0, %1;" : "=r"(u) : "f"(x));
    return __uint_as_float(u);
}

__device__ __forceinline__ void mma_tf32(float c[4], const uint32_t a[4], const uint32_t b[2]) {
    asm volatile(
        "mma.sync.aligned.m16n8k8.row.col.f32.tf32.tf32.f32 "
        "{%0,%1,%2,%3}, {%4,%5,%6,%7}, {%8,%9}, {%0,%1,%2,%3};"
        : "+f"(c[0]), "+f"(c[1]), "+f"(c[2]), "+f"(c[3])
        : "r"(a[0]), "r"(a[1]), "r"(a[2]), "r"(a[3]), "r"(b[0]), "r"(b[1]));
}

__device__ __forceinline__ void cp16(uint32_t smem_addr, const float* gptr) {
    asm volatile("cp.async.cg.shared.global [%0], [%1], 16;"
                 :: "r"(smem_addr), "l"(gptr) : "memory");
}
__device__ __forceinline__ void cp_commit() {
    asm volatile("cp.async.commit_group;" ::: "memory");
}
template<int N>
__device__ __forceinline__ void cp_wait() {
    asm volatile("cp.async.wait_group %0;" :: "n"(N) : "memory");
}

// ---------------------------------------------------------------------------
// Fragment-major permute of A (x)
// ---------------------------------------------------------------------------
__global__ __launch_bounds__(256) void perm_a_kernel(const float* __restrict__ src)
{
    const int total = M16 * 32 * 32;
    int idx = blockIdx.x * blockDim.x + threadIdx.x;
    int stride = gridDim.x * blockDim.x;
    for (; idx < total; idx += stride) {
        int lane = idx & 31;
        int k8 = (idx >> 5) & 31;
        int m16 = idx >> 10;
        int g = lane >> 2, t = lane & 3;
        size_t r0 = (size_t)(m16 * 16 + g) * 256;
        int c0 = k8 * 8 + t;
        float4 o;
        o.x = to_tf32(src[r0 + c0]);
        o.y = to_tf32(src[r0 + 8 * 256 + c0]);
        o.z = to_tf32(src[r0 + c0 + 4]);
        o.w = to_tf32(src[r0 + 8 * 256 + c0 + 4]);
        ((float4*)g_xperm)[idx] = o;
    }
}

// ---------------------------------------------------------------------------
// Fragment-major permute of B weights (0 -> g_wqp, 1 -> g_wpp)
// ---------------------------------------------------------------------------
__global__ __launch_bounds__(256) void perm_b_kernel(
    const float* __restrict__ src, int n8_count, int which)
{
    float* dst = (which == 0) ? g_wqp : g_wpp;
    const int total = n8_count * 32 * 32;
    int idx = blockIdx.x * blockDim.x + threadIdx.x;
    int stride = gridDim.x * blockDim.x;
    for (; idx < total; idx += stride) {
        int lane = idx & 31;
        int k8 = (idx >> 5) & 31;
        int n8 = idx >> 10;
        int g = lane >> 2, t = lane & 3;
        size_t n = (size_t)(n8 * 8 + g) * 256;
        int c = k8 * 8 + t;
        float2 o;
        o.x = to_tf32(src[n + c]);
        o.y = to_tf32(src[n + c + 4]);
        ((float2*)dst)[idx] = o;
    }
}

// ---------------------------------------------------------------------------
// QKV GEMM (proven mainloop). Epilogue scatters q row-major, k/v fragment-major.
// ---------------------------------------------------------------------------
#define QKV_SMEM 65536

__global__ __launch_bounds__(128) void gemm_qkv_perm(
    const float* __restrict__ bias)
{
    extern __shared__ float sm[];
    const uint32_t sm_u32 = (uint32_t)__cvta_generic_to_shared(sm);
    const uint32_t sB_u32 = sm_u32 + 2 * 4096 * 4;

    const int tid = threadIdx.x;
    const int mb16 = blockIdx.y * 8;
    const int nb8  = blockIdx.x * 16;

    const int warp = tid >> 5, lane = tid & 31;
    const int wm16 = (warp & 1) * 4;
    const int wn8  = (warp >> 1) * 8;

    const int a_m16l = tid >> 4, a_in = tid & 15;
    const int b_n8l = tid >> 3, b_in = tid & 7;

    auto issue = [&](int ks, int buf) {
        const float* agm = g_xperm + (size_t)(mb16 + a_m16l) * 4096 + ks * 512;
        uint32_t adst = sm_u32 + (uint32_t)((buf * 4096 + a_m16l * 512) * 4);
#pragma unroll
        for (int j = 0; j < 8; j++) {
            int ch = a_in + j * 16;
            cp16(adst + ch * 16, agm + ch * 4);
        }
        const float* bgm = g_wqp + (size_t)(nb8 + b_n8l) * 2048 + ks * 256;
        uint32_t bdst = sB_u32 + (uint32_t)((buf * 4096 + b_n8l * 256) * 4);
#pragma unroll
        for (int j = 0; j < 8; j++) {
            int ch = b_in + j * 8;
            cp16(bdst + ch * 16, bgm + ch * 4);
        }
        cp_commit();
    };

    float acc[4][8][4] = {};

    issue(0, 0);
    for (int ks = 0; ks < 8; ks++) {
        const int buf = ks & 1;
        if (ks < 7) issue(ks + 1, buf ^ 1);
        if (ks < 7) cp_wait<1>(); else cp_wait<0>();
        __syncthreads();

        const float* As = sm + buf * 4096;
        const float* Bs = sm + 2 * 4096 + buf * 4096;

#pragma unroll
        for (int k8l = 0; k8l < 4; k8l++) {
            uint32_t a[4][4], bb[8][2];
#pragma unroll
            for (int mi = 0; mi < 4; mi++) {
                const float4 av = *(const float4*)(As + (wm16 + mi) * 512 + k8l * 128 + lane * 4);
                a[mi][0] = __float_as_uint(av.x);
                a[mi][1] = __float_as_uint(av.y);
                a[mi][2] = __float_as_uint(av.z);
                a[mi][3] = __float_as_uint(av.w);
            }
#pragma unroll
            for (int ni = 0; ni < 8; ni++) {
                const float2 bv = *(const float2*)(Bs + (wn8 + ni) * 256 + k8l * 64 + lane * 2);
                bb[ni][0] = __float_as_uint(bv.x);
                bb[ni][1] = __float_as_uint(bv.y);
            }
#pragma unroll
            for (int mi = 0; mi < 4; mi++)
#pragma unroll
                for (int ni = 0; ni < 8; ni++)
                    mma_tf32(acc[mi][ni], a[mi], bb[ni]);
        }
        __syncthreads();
    }

    // epilogue: q row-major; k/v fragment-major for attention
    const float qscale = 0.17677669529663687f;
    const int g = lane >> 2, t = lane & 3;
    const int wm = (warp & 1) * 64, wn = (warp >> 1) * 64;
    const int mBase = blockIdx.y * 128, nBase = blockIdx.x * 128;
#pragma unroll
    for (int mi = 0; mi < 4; mi++) {
#pragma unroll
        for (int ni = 0; ni < 8; ni++) {
            int gn = nBase + wn + ni * 8 + t * 2;
            float bv0 = bias[gn], bv1 = bias[gn + 1];
            int which = gn >> 8;
            int h = (gn >> 5) & 7;
            int d = gn & 31;            // even, d%8 = 2t
            float sc = (which == 0) ? qscale : 1.0f;
#pragma unroll
            for (int half = 0; half < 2; half++) {
                int gm = mBase + wm + mi * 16 + g + half * 8;
                int b = gm / 49;
                int r = gm - b * 49;
                float v0 = to_tf32((acc[mi][ni][half * 2 + 0] + bv0) * sc);
                float v1 = to_tf32((acc[mi][ni][half * 2 + 1] + bv1) * sc);
                float* slab = g_qkv + ((size_t)b * 8 + h) * QKV_SLAB;
                if (which == 0) {
                    *(float2*)(slab + r * 32 + d) = make_float2(v0, v1);
                } else if (which == 1) {
                    // k fragment: element (j=r, d): lane=(j%8)*4+tk, slot=(d%8>=4)
                    int tj = r >> 3, jg = r & 7;
                    int kc = (d >> 3) & 3;
                    int rd = d & 7;           // 2t
                    int slot = rd >> 2;       // both d,d+1 share slot
                    int tk = rd - slot * 4;
                    float* base = slab + KF_OFF + (tj * 4 + kc) * 64 + slot;
                    base[(jg * 4 + tk) * 2]     = v0;
                    base[(jg * 4 + tk + 1) * 2] = v1;
                } else {
                    // v fragment: element (j=r, d): lane=(d%8)*4+rjk, slot=(j%8>=4)
                    int kc = r >> 3, rj = r & 7;
                    int nt = (d >> 3) & 3;
                    int rd = d & 7;           // 2t
                    int slot = rj >> 2;
                    int rjk = rj - slot * 4;
                    float* base = slab + VF_OFF + (nt * 7 + kc) * 64 + slot;
                    base[(rd * 4 + rjk) * 2]       = v0;
                    base[((rd + 1) * 4 + rjk) * 2] = v1;
                }
            }
        }
    }
}

// ---------------------------------------------------------------------------
// Proj GEMM (proven R16): A = g_attn row-major slabs, B = g_wpp fragment-major
// ---------------------------------------------------------------------------
#define PROJ_SMEM (36864 + 32768)

__global__ __launch_bounds__(128) void gemm_proj_fm(
    const float* __restrict__ bias, float* __restrict__ out)
{
    extern __shared__ float sm[];
    const uint32_t sm_u32 = (uint32_t)__cvta_generic_to_shared(sm);
    const uint32_t sB_u32 = sm_u32 + 2 * 128 * 36 * 4;

    const int tid = threadIdx.x;
    const int mBase = blockIdx.y * 128;
    const int nb8  = blockIdx.x * 16;
    const int nBase = blockIdx.x * 128;

    const int warp = tid >> 5, lane = tid & 31;
    const int wm = (warp & 1) * 64, wn8 = (warp >> 1) * 8;
    const int g = lane >> 2, t = lane & 3;

    const int r0 = tid >> 3;
    const int c0 = (tid & 7) * 4;
    const int b_n8l = tid >> 3, b_in = tid & 7;

    auto issue = [&](int ks, int buf) {
        const float* xrow = g_attn + (size_t)(mBase + r0) * 256 + ks * 32 + c0;
        uint32_t adst = sm_u32 + (uint32_t)((buf * 128 * 36 + r0 * 36 + c0) * 4);
#pragma unroll
        for (int p = 0; p < 8; p++) {
            cp16(adst + p * 16 * 36 * 4, xrow + (size_t)p * 16 * 256);
        }
        const float* bgm = g_wpp + (size_t)(nb8 + b_n8l) * 2048 + ks * 256;
        uint32_t bdst = sB_u32 + (uint32_t)((buf * 4096 + b_n8l * 256) * 4);
#pragma unroll
        for (int j = 0; j < 8; j++) {
            int ch = b_in + j * 8;
            cp16(bdst + ch * 16, bgm + ch * 4);
        }
        cp_commit();
    };

    float acc[4][8][4] = {};

    issue(0, 0);
    for (int ks = 0; ks < 8; ks++) {
        const int buf = ks & 1;
        if (ks < 7) issue(ks + 1, buf ^ 1);
        if (ks < 7) cp_wait<1>(); else cp_wait<0>();
        __syncthreads();

        const float* As = sm + buf * 128 * 36;
        const float* Bs = sm + 2 * 128 * 36 + buf * 4096;

#pragma unroll
        for (int k8l = 0; k8l < 4; k8l++) {
            const int ko = k8l * 8;
            uint32_t a[4][4], bb[8][2];
#pragma unroll
            for (int mi = 0; mi < 4; mi++) {
                int row = wm + mi * 16 + g;
                a[mi][0] = __float_as_uint(As[row * 36 + ko + t]);
                a[mi][1] = __float_as_uint(As[(row + 8) * 36 + ko + t]);
                a[mi][2] = __float_as_uint(As[row * 36 + ko + t + 4]);
                a[mi][3] = __float_as_uint(As[(row + 8) * 36 + ko + t + 4]);
            }
#pragma unroll
            for (int ni = 0; ni < 8; ni++) {
                const float2 bv = *(const float2*)(Bs + (wn8 + ni) * 256 + k8l * 64 + lane * 2);
                bb[ni][0] = __float_as_uint(bv.x);
                bb[ni][1] = __float_as_uint(bv.y);
            }
#pragma unroll
            for (int mi = 0; mi < 4; mi++)
#pragma unroll
                for (int ni = 0; ni < 8; ni++)
                    mma_tf32(acc[mi][ni], a[mi], bb[ni]);
        }
        __syncthreads();
    }

    const int wn = (warp >> 1) * 64;
#pragma unroll
    for (int mi = 0; mi < 4; mi++) {
#pragma unroll
        for (int ni = 0; ni < 8; ni++) {
            int gn = nBase + wn + ni * 8 + t * 2;
            float bv0 = bias[gn], bv1 = bias[gn + 1];
#pragma unroll
            for (int half = 0; half < 2; half++) {
                int gm = mBase + wm + mi * 16 + g + half * 8;
                float v0 = acc[mi][ni][half * 2 + 0] + bv0;
                float v1 = acc[mi][ni][half * 2 + 1] + bv1;
                *(float2*)(out + (size_t)gm * 256 + gn) = make_float2(v0, v1);
            }
        }
    }
}

// ---------------------------------------------------------------------------
// Kernel 0: fuse bias_table + mask -> g_bm[(w*8+h)][i*56+j]
// ---------------------------------------------------------------------------
__global__ __launch_bounds__(256) void fuse_bm_kernel(
    const float* __restrict__ mask, const float* __restrict__ bt)
{
    const int wh = blockIdx.x;
    const int w = wh >> 3, h = wh & 7;
    const float* mw = mask + (size_t)w * 2401;
    float* dst = g_bm + (size_t)wh * BM_SLAB;
    for (int idx = threadIdx.x; idx < 2401; idx += 256) {
        int i = idx / 49, j = idx - i * 49;
        int ri = i / 7, ci = i - ri * 7;
        int rj = j / 7, cj = j - rj * 7;
        int bidx = (ri - rj + 6) * 13 + (ci - cj + 6);
        dst[i * BM_STRIDE + j] = mw[idx] + bt[bidx * 8 + h];
    }
}

// ---------------------------------------------------------------------------
// Slim tensor-core attention: k/v via coalesced fragment-major LDG.64;
// no-max softmax (values bounded); all inputs pre-tf32.
// ---------------------------------------------------------------------------
__global__ __launch_bounds__(64) void attn_slim_kernel()
{
    __shared__ float sP[2 * 32 * 60];

    const int bh   = blockIdx.x;
    const int b    = bh >> 3;
    const int h    = bh & 7;
    const int warp = threadIdx.x >> 5;
    const int lane = threadIdx.x & 31;
    const int g = lane >> 2, t = lane & 3;

    const float* slab = g_qkv + (size_t)bh * QKV_SLAB;
    const float* qb = slab;
    const float* kf = slab + KF_OFF;
    const float* vf = slab + VF_OFF;

    // ---- S = q @ k^T ----
    float acc[2][7][4] = {};
#pragma unroll
    for (int kc = 0; kc < 4; kc++) {
        uint32_t a[2][4];
#pragma unroll
        for (int mt = 0; mt < 2; mt++) {
            const float* qr = qb + (warp * 32 + mt * 16 + g) * 32 + kc * 8;
            a[mt][0] = __float_as_uint(qr[t]);
            a[mt][1] = __float_as_uint(qr[8 * 32 + t]);
            a[mt][2] = __float_as_uint(qr[t + 4]);
            a[mt][3] = __float_as_uint(qr[8 * 32 + t + 4]);
        }
#pragma unroll
        for (int tj = 0; tj < 7; tj++) {
            const float2 kv2 = *(const float2*)(kf + (tj * 4 + kc) * 64 + lane * 2);
            uint32_t bb[2];
            bb[0] = __float_as_uint(kv2.x);
            bb[1] = __float_as_uint(kv2.y);
            mma_tf32(acc[0][tj], a[0], bb);
            mma_tf32(acc[1][tj], a[1], bb);
        }
    }

    // ---- no-max softmax with fused bias+mask, P -> sP (tf32) ----
    const float* bmp = g_bm + ((size_t)((b & 63) * 8 + h)) * BM_SLAB;
    float* sP_w = sP + warp * 32 * 60;
#pragma unroll
    for (int mt = 0; mt < 2; mt++) {
#pragma unroll
        for (int rh = 0; rh < 2; rh++) {
            int irow = warp * 32 + mt * 16 + g + rh * 8;
            bool vi = (irow < 49);
            const float* bmr = bmp + irow * BM_STRIDE;
            float vals[14];
            float ssum = 0.f;
#pragma unroll
            for (int tj = 0; tj < 7; tj++) {
                float2 bm2 = vi ? *(const float2*)(bmr + tj * 8 + 2 * t)
                                : make_float2(0.f, 0.f);
#pragma unroll
                for (int cc = 0; cc < 2; cc++) {
                    int j = tj * 8 + 2 * t + cc;
                    float e = 0.f;
                    if (vi && j < 49)
                        e = __expf(acc[mt][tj][rh * 2 + cc] + (cc ? bm2.y : bm2.x));
                    vals[tj * 2 + cc] = e;
                    ssum += e;
                }
            }
            ssum += __shfl_xor_sync(0xffffffffu, ssum, 1);
            ssum += __shfl_xor_sync(0xffffffffu, ssum, 2);
            float inv = __frcp_rn(ssum);   // rows >=49: inf; 0*inf=NaN, discarded at store
            float* prow = sP_w + (mt * 16 + g + rh * 8) * 60;
#pragma unroll
            for (int tj = 0; tj < 7; tj++) {
                float2 p2 = make_float2(to_tf32(vals[tj * 2] * inv),
                                        to_tf32(vals[tj * 2 + 1] * inv));
                *(float2*)(prow + tj * 8 + 2 * t) = p2;
            }
        }
    }
    __syncwarp();

    // ---- out = P @ v : v via fragment-major LDG.64 (pad slots are zeros) ----
    float pacc[2][4][4] = {};
#pragma unroll
    for (int kc = 0; kc < 7; kc++) {
        uint32_t a[2][4];
#pragma unroll
        for (int mt = 0; mt < 2; mt++) {
            const float* pr = sP_w + (mt * 16 + g) * 60 + kc * 8;
            a[mt][0] = __float_as_uint(pr[t]);
            a[mt][1] = __float_as_uint(pr[8 * 60 + t]);
            a[mt][2] = __float_as_uint(pr[t + 4]);
            a[mt][3] = __float_as_uint(pr[8 * 60 + t + 4]);
        }
#pragma unroll
        for (int nt = 0; nt < 4; nt++) {
            const float2 vv2 = *(const float2*)(vf + (nt * 7 + kc) * 64 + lane * 2);
            uint32_t bb[2];
            bb[0] = __float_as_uint(vv2.x);
            bb[1] = __float_as_uint(vv2.y);
            mma_tf32(pacc[0][nt], a[0], bb);
            mma_tf32(pacc[1][nt], a[1], bb);
        }
    }

    // ---- store rows i < 49, tf32-rounded for proj ----
#pragma unroll
    for (int mt = 0; mt < 2; mt++) {
#pragma unroll
        for (int rh = 0; rh < 2; rh++) {
            int irow = warp * 32 + mt * 16 + g + rh * 8;
            if (irow < 49) {
                float* op = g_attn + ((size_t)b * 49 + irow) * 256 + h * 32;
#pragma unroll
                for (int nt = 0; nt < 4; nt++) {
                    int d = nt * 8 + 2 * t;
                    *(float2*)(op + d) =
                        make_float2(to_tf32(pacc[mt][nt][rh * 2 + 0]),
                                    to_tf32(pacc[mt][nt][rh * 2 + 1]));
                }
            }
        }
    }
}

// ---------------------------------------------------------------------------
extern "C" void kernel_launch(void* const* d_in, const int* in_sizes, int n_in,
                              void* d_out, int out_size)
{
    const float* x      = (const float*)d_in[0];
    const float* mask   = (const float*)d_in[1];
    const float* qkv_w  = (const float*)d_in[2];
    const float* qkv_b  = (const float*)d_in[3];
    const float* proj_w = (const float*)d_in[4];
    const float* proj_b = (const float*)d_in[5];
    const float* bt     = (const float*)d_in[6];
    float* out = (float*)d_out;

    cudaFuncSetAttribute((const void*)gemm_qkv_perm,
                         cudaFuncAttributeMaxDynamicSharedMemorySize, QKV_SMEM);
    cudaFuncSetAttribute((const void*)gemm_proj_fm,
                         cudaFuncAttributeMaxDynamicSharedMemorySize, PROJ_SMEM);

    perm_a_kernel<<<2048, 256>>>(x);
    perm_b_kernel<<<384, 256>>>(qkv_w, 96, 0);
    perm_b_kernel<<<128, 256>>>(proj_w, 32, 1);
    fuse_bm_kernel<<<512, 256>>>(mask, bt);

    gemm_qkv_perm<<<dim3(6, M_ROWS / 128), 128, QKV_SMEM>>>(qkv_b);
    attn_slim_kernel<<<B_WIN * H_NUM, 64>>>();
    gemm_proj_fm<<<dim3(2, M_ROWS / 128), 128, PROJ_SMEM>>>(proj_b, out);
}